// round 1
// baseline (speedup 1.0000x reference)
#include <cuda_runtime.h>
#include <math.h>

// Problem constants (fixed by the reference)
#define NTOT 8192   // B * A
#define BATCH 512
#define NADV 16
#define DIN 64      // DS + DO
#define HID 128

// Scratch (device globals; no allocation allowed)
__device__ float g_x[NTOT * DIN];     // mlp_input
__device__ float g_h1[NTOT * HID];    // relu(mlp_input @ hw1 + hb1)
__device__ float g_emb[NTOT * HID];   // tanh(einsum)
__device__ float g_vh[NTOT * HID];    // value MLP hidden
__device__ float g_vals[NTOT * HID];  // value MLP out
__device__ float g_mean[BATCH * HID]; // per-batch mean embedding
__device__ float g_a1[NTOT * HID];    // attention hidden 1
__device__ float g_a2[NTOT * HID];    // attention hidden 2
__device__ float g_sc[NTOT];          // attention scores

// ---------------------------------------------------------------------------
// Kernel 1: build mlp_input and h1 = relu(mlp_input @ hw1 + hb1)
// 16 rows per CTA, 256 threads. hw1 (64x128, 32KB) staged in smem.
// ---------------------------------------------------------------------------
__global__ __launch_bounds__(256) void k_build_h1(
    const float* __restrict__ obs, const float* __restrict__ lat,
    const float* __restrict__ hw1, const float* __restrict__ hb1) {
    __shared__ __align__(16) float sw[DIN][HID];
    __shared__ float sb[HID];
    __shared__ float sx[16][DIN];
    int tid = threadIdx.x;
    int n0 = blockIdx.x * 16;

    for (int i = tid; i < DIN * HID; i += 256) ((float*)sw)[i] = hw1[i];
    if (tid < HID) sb[tid] = hb1[tid];
    for (int i = tid; i < 16 * DIN; i += 256) {
        int r = i >> 6, d = i & 63;
        int n = n0 + r;
        // self_rep row n = obs[n % 512]; obstacle row n = latent_flat[n]
        float v = (d < 32) ? obs[(n & 511) * 32 + d] : lat[n * 32 + (d - 32)];
        sx[r][d] = v;
        g_x[n * DIN + d] = v;
    }
    __syncthreads();

    int r = tid >> 4, cg = tid & 15;   // 16 rows x 16 col-groups of 8
    float acc[8];
#pragma unroll
    for (int c = 0; c < 8; c++) acc[c] = 0.f;
#pragma unroll 8
    for (int d = 0; d < DIN; d++) {
        float a = sx[r][d];
        float4 w0 = *(const float4*)&sw[d][cg * 8];
        float4 w1 = *(const float4*)&sw[d][cg * 8 + 4];
        acc[0] += a * w0.x; acc[1] += a * w0.y;
        acc[2] += a * w0.z; acc[3] += a * w0.w;
        acc[4] += a * w1.x; acc[5] += a * w1.y;
        acc[6] += a * w1.z; acc[7] += a * w1.w;
    }
    int n = n0 + r;
#pragma unroll
    for (int c = 0; c < 8; c++) {
        float v = acc[c] + sb[cg * 8 + c];
        g_h1[n * HID + cg * 8 + c] = fmaxf(v, 0.f);
    }
}

// ---------------------------------------------------------------------------
// Kernel 2 (the monster): fused hypernet second layer + einsum + tanh.
// Per CTA: 64 rows. For d in [0,64): S = Htile[64,128] @ hw2[:, d*128:(d+1)*128]
//   emb += x[:,d] * relu(S + hb2[d*128:..])   -> g_emb = tanh(emb)
// 17.2 GF total, [8192,8192] intermediate never materialized.
// smem: Hs transposed [k][row] 32KB + Ws chunk [32][128] 16KB = 48KB.
// ---------------------------------------------------------------------------
__global__ __launch_bounds__(256, 1) void k_hyper(
    const float* __restrict__ hw2, const float* __restrict__ hb2) {
    __shared__ __align__(16) float Hs[HID][64];  // [k][row]
    __shared__ __align__(16) float Ws[32][HID];  // [k][col]
    int tid = threadIdx.x;
    int n0 = blockIdx.x * 64;

    // Load H tile transposed (smem-coalesced writes; gmem reads L2-served)
    for (int i = tid; i < 64 * HID; i += 256) {
        int row = i & 63, k = i >> 6;
        Hs[k][row] = g_h1[(n0 + row) * HID + k];
    }

    int tr = tid >> 4, tc = tid & 15;  // 16x16 thread grid; micro-tile 4x8
    float emb[4][8];
#pragma unroll
    for (int a = 0; a < 4; a++)
#pragma unroll
        for (int b = 0; b < 8; b++) emb[a][b] = 0.f;

    for (int d = 0; d < DIN; d++) {
        float acc[4][8];
#pragma unroll
        for (int a = 0; a < 4; a++)
#pragma unroll
            for (int b = 0; b < 8; b++) acc[a][b] = 0.f;

        for (int kc = 0; kc < 4; kc++) {
            __syncthreads();
            // stage hw2 rows kc*32..+32, cols d*128..+128 (16KB)
            for (int i = tid; i < 32 * HID; i += 256) {
                int kk = i >> 7, c = i & 127;
                Ws[kk][c] = hw2[(kc * 32 + kk) * 8192 + d * HID + c];
            }
            __syncthreads();
#pragma unroll
            for (int k = 0; k < 32; k++) {
                float4 av4 = *(const float4*)&Hs[kc * 32 + k][tr * 4];
                float4 b0 = *(const float4*)&Ws[k][tc * 8];
                float4 b1 = *(const float4*)&Ws[k][tc * 8 + 4];
                float a_[4] = {av4.x, av4.y, av4.z, av4.w};
                float b_[8] = {b0.x, b0.y, b0.z, b0.w, b1.x, b1.y, b1.z, b1.w};
#pragma unroll
                for (int rr = 0; rr < 4; rr++)
#pragma unroll
                    for (int cc = 0; cc < 8; cc++)
                        acc[rr][cc] += a_[rr] * b_[cc];
            }
        }
        // epilogue for this d: relu(S + bias) weighted by x[:,d]
        float bias[8];
#pragma unroll
        for (int cc = 0; cc < 8; cc++) bias[cc] = hb2[d * HID + tc * 8 + cc];
#pragma unroll
        for (int rr = 0; rr < 4; rr++) {
            float xv = g_x[(n0 + tr * 4 + rr) * DIN + d];
#pragma unroll
            for (int cc = 0; cc < 8; cc++) {
                float s = fmaxf(acc[rr][cc] + bias[cc], 0.f);
                emb[rr][cc] += xv * s;
            }
        }
    }
#pragma unroll
    for (int rr = 0; rr < 4; rr++)
#pragma unroll
        for (int cc = 0; cc < 8; cc++)
            g_emb[(n0 + tr * 4 + rr) * HID + tc * 8 + cc] = tanhf(emb[rr][cc]);
}

// ---------------------------------------------------------------------------
// Generic fused linear: out[N,128] = act(A[N,K] @ W[K,128] + bias)
// CONCAT: A(n,k) = k<128 ? A[n,k] : A2[n%512, k-128] (attention input concat)
// 64 rows per CTA, 256 threads, 4x8 micro-tiles.
// ---------------------------------------------------------------------------
template <bool CONCAT>
__global__ __launch_bounds__(256) void k_mlp(
    const float* __restrict__ A, const float* __restrict__ A2,
    const float* __restrict__ W, const float* __restrict__ bias,
    float* __restrict__ out, int K, int do_relu) {
    __shared__ __align__(16) float As[32][68];  // [k][row], padded
    __shared__ __align__(16) float Ws[32][HID];
    int tid = threadIdx.x;
    int n0 = blockIdx.x * 64;
    int tr = tid >> 4, tc = tid & 15;

    float acc[4][8];
#pragma unroll
    for (int a = 0; a < 4; a++)
#pragma unroll
        for (int b = 0; b < 8; b++) acc[a][b] = 0.f;

    int nkc = K >> 5;
    for (int kc = 0; kc < nkc; kc++) {
        __syncthreads();
        for (int i = tid; i < 64 * 32; i += 256) {
            int row = i >> 5, kk = i & 31;
            int n = n0 + row;
            int kg = kc * 32 + kk;
            float v;
            if (CONCAT)
                v = (kg < HID) ? A[n * HID + kg]
                               : A2[(n & 511) * HID + (kg - HID)];
            else
                v = A[n * K + kg];
            As[kk][row] = v;
        }
        for (int i = tid; i < 32 * HID; i += 256) {
            int kk = i >> 7, c = i & 127;
            Ws[kk][c] = W[(kc * 32 + kk) * HID + c];
        }
        __syncthreads();
#pragma unroll
        for (int k = 0; k < 32; k++) {
            float4 av4 = *(const float4*)&As[k][tr * 4];
            float4 b0 = *(const float4*)&Ws[k][tc * 8];
            float4 b1 = *(const float4*)&Ws[k][tc * 8 + 4];
            float a_[4] = {av4.x, av4.y, av4.z, av4.w};
            float b_[8] = {b0.x, b0.y, b0.z, b0.w, b1.x, b1.y, b1.z, b1.w};
#pragma unroll
            for (int rr = 0; rr < 4; rr++)
#pragma unroll
                for (int cc = 0; cc < 8; cc++)
                    acc[rr][cc] += a_[rr] * b_[cc];
        }
    }
#pragma unroll
    for (int rr = 0; rr < 4; rr++) {
        int n = n0 + tr * 4 + rr;
#pragma unroll
        for (int cc = 0; cc < 8; cc++) {
            float v = acc[rr][cc] + bias[tc * 8 + cc];
            if (do_relu) v = fmaxf(v, 0.f);
            out[n * HID + tc * 8 + cc] = v;
        }
    }
}

// ---------------------------------------------------------------------------
// emb_mean[b,h] = mean over a=0..15 of emb[b*16+a, h]
// ---------------------------------------------------------------------------
__global__ void k_mean() {
    int idx = blockIdx.x * 256 + threadIdx.x;  // 65536 total
    int b = idx >> 7, h = idx & 127;
    float s = 0.f;
#pragma unroll
    for (int a = 0; a < NADV; a++) s += g_emb[((b << 4) + a) * HID + h];
    g_mean[idx] = s * (1.f / 16.f);
}

// ---------------------------------------------------------------------------
// scores[n] = g_a2[n,:] . aw3 + ab3   (one warp per row)
// ---------------------------------------------------------------------------
__global__ void k_score(const float* __restrict__ A,
                        const float* __restrict__ w,
                        const float* __restrict__ b) {
    int warp = threadIdx.x >> 5, lane = threadIdx.x & 31;
    int n = blockIdx.x * 8 + warp;
    float s = 0.f;
#pragma unroll
    for (int k = lane; k < HID; k += 32) s += A[n * HID + k] * w[k];
#pragma unroll
    for (int off = 16; off; off >>= 1) s += __shfl_xor_sync(0xffffffffu, s, off);
    if (lane == 0) g_sc[n] = s + b[0];
}

// ---------------------------------------------------------------------------
// Softmax over groups of 16 + weighted sum of vals -> out[512,128]
// ---------------------------------------------------------------------------
__global__ void k_final(float* __restrict__ out) {
    __shared__ float sc[NADV];
    int b = blockIdx.x, tid = threadIdx.x;  // 128 threads = H
    if (tid < NADV) sc[tid] = g_sc[b * NADV + tid];
    __syncthreads();
    float m = sc[0];
#pragma unroll
    for (int a = 1; a < NADV; a++) m = fmaxf(m, sc[a]);
    float den = 0.f, o = 0.f;
#pragma unroll
    for (int a = 0; a < NADV; a++) {
        float e = expf(sc[a] - m);
        den += e;
        o += e * g_vals[(b * NADV + a) * HID + tid];
    }
    out[b * HID + tid] = o / den;
}

// ---------------------------------------------------------------------------
extern "C" void kernel_launch(void* const* d_in, const int* in_sizes, int n_in,
                              void* d_out, int out_size) {
    const float* obs = (const float*)d_in[0];
    const float* lat = (const float*)d_in[1];
    const float* hw1 = (const float*)d_in[2];
    const float* hb1 = (const float*)d_in[3];
    const float* hw2 = (const float*)d_in[4];
    const float* hb2 = (const float*)d_in[5];
    const float* vw1 = (const float*)d_in[6];
    const float* vb1 = (const float*)d_in[7];
    const float* vw2 = (const float*)d_in[8];
    const float* vb2 = (const float*)d_in[9];
    const float* aw1 = (const float*)d_in[10];
    const float* ab1 = (const float*)d_in[11];
    const float* aw2 = (const float*)d_in[12];
    const float* ab2 = (const float*)d_in[13];
    const float* aw3 = (const float*)d_in[14];
    const float* ab3 = (const float*)d_in[15];
    float* out = (float*)d_out;

    // Resolve scratch symbol addresses (host-side, capture-safe, no allocs)
    float *p_emb, *p_vh, *p_vals, *p_mean, *p_a1, *p_a2;
    cudaGetSymbolAddress((void**)&p_emb, g_emb);
    cudaGetSymbolAddress((void**)&p_vh, g_vh);
    cudaGetSymbolAddress((void**)&p_vals, g_vals);
    cudaGetSymbolAddress((void**)&p_mean, g_mean);
    cudaGetSymbolAddress((void**)&p_a1, g_a1);
    cudaGetSymbolAddress((void**)&p_a2, g_a2);

    // 1. mlp_input + h1
    k_build_h1<<<NTOT / 16, 256>>>(obs, lat, hw1, hb1);
    // 2. fused hypernet GEMM + einsum + tanh -> emb
    k_hyper<<<NTOT / 64, 256>>>(hw2, hb2);
    // 3. value MLP
    k_mlp<false><<<NTOT / 64, 256>>>(p_emb, nullptr, vw1, vb1, p_vh, 128, 1);
    k_mlp<false><<<NTOT / 64, 256>>>(p_vh, nullptr, vw2, vb2, p_vals, 128, 1);
    // 4. mean embedding
    k_mean<<<(BATCH * HID) / 256, 256>>>();
    // 5. attention MLP (concat input, K=256)
    k_mlp<true><<<NTOT / 64, 256>>>(p_emb, p_mean, aw1, ab1, p_a1, 256, 1);
    k_mlp<false><<<NTOT / 64, 256>>>(p_a1, nullptr, aw2, ab2, p_a2, 128, 1);
    k_score<<<NTOT / 8, 256>>>(p_a2, aw3, ab3);
    // 6. softmax + weighted sum
    k_final<<<BATCH, HID>>>(out);
}

// round 3
// speedup vs baseline: 3.3771x; 3.3771x over previous
#include <cuda_runtime.h>
#include <cuda_bf16.h>
#include <math.h>
#include <stdint.h>

// Problem constants
#define NTOT 8192   // B * A
#define BATCH 512
#define NADV 16
#define DIN 64      // DS + DO
#define HID 128

// Scratch
__device__ float g_x[NTOT * DIN];
__device__ float g_h1[NTOT * HID];
__device__ float g_emb[NTOT * HID];
__device__ float g_embp[2 * NTOT * HID];   // partial einsum sums (pre-tanh)
__device__ float g_vh[NTOT * HID];
__device__ float g_vals[NTOT * HID];
__device__ float g_mean[BATCH * HID];
__device__ float g_a1[NTOT * HID];
__device__ float g_a2[NTOT * HID];
__device__ float g_sc[NTOT];
// Pre-converted B tiles: per d (64), Bt[n=128][k=264 bf16] (hi k:0..127, lo 128..255, 8 pad)
// row pitch 528B; tile = 67584B = 4224 uint4
__device__ uint4 g_bbf[64 * 4224];

// ---------------------------------------------------------------------------
// helpers
// ---------------------------------------------------------------------------
__device__ __forceinline__ uint32_t smem_u32(const void* p) {
    uint32_t a;
    asm("{ .reg .u64 t; cvta.to.shared.u64 t, %1; cvt.u32.u64 %0, t; }" : "=r"(a) : "l"(p));
    return a;
}
__device__ __forceinline__ void f2hl(float v, uint16_t& h, uint16_t& l) {
    __nv_bfloat16 bh = __float2bfloat16_rn(v);
    float r = v - __bfloat162float(bh);
    __nv_bfloat16 bl = __float2bfloat16_rn(r);
    h = __bfloat16_as_ushort(bh);
    l = __bfloat16_as_ushort(bl);
}
__device__ __forceinline__ void ldsm_x4(uint32_t* r, uint32_t addr) {
    asm volatile("ldmatrix.sync.aligned.m8n8.x4.shared.b16 {%0,%1,%2,%3}, [%4];"
                 : "=r"(r[0]), "=r"(r[1]), "=r"(r[2]), "=r"(r[3]) : "r"(addr));
}
__device__ __forceinline__ void mma16816(float* d, const uint32_t* a, uint32_t b0, uint32_t b1) {
    asm volatile(
        "mma.sync.aligned.m16n8k16.row.col.f32.bf16.bf16.f32 "
        "{%0,%1,%2,%3}, {%4,%5,%6,%7}, {%8,%9}, {%0,%1,%2,%3};"
        : "+f"(d[0]), "+f"(d[1]), "+f"(d[2]), "+f"(d[3])
        : "r"(a[0]), "r"(a[1]), "r"(a[2]), "r"(a[3]), "r"(b0), "r"(b1));
}
__device__ __forceinline__ void cp16(uint32_t dst, const void* src) {
    asm volatile("cp.async.cg.shared.global [%0], [%1], 16;" :: "r"(dst), "l"(src) : "memory");
}
#define CP_COMMIT() asm volatile("cp.async.commit_group;" ::: "memory")
#define CP_WAIT(N)  asm volatile("cp.async.wait_group %0;" :: "n"(N) : "memory")

// ---------------------------------------------------------------------------
// Kernel 1: build mlp_input and h1 = relu(x @ hw1 + hb1)
// ---------------------------------------------------------------------------
__global__ __launch_bounds__(256) void k_build_h1(
    const float* __restrict__ obs, const float* __restrict__ lat,
    const float* __restrict__ hw1, const float* __restrict__ hb1) {
    __shared__ __align__(16) float sw[DIN][HID];
    __shared__ float sb[HID];
    __shared__ float sx[16][DIN];
    int tid = threadIdx.x;
    int n0 = blockIdx.x * 16;

    for (int i = tid; i < DIN * HID; i += 256) ((float*)sw)[i] = hw1[i];
    if (tid < HID) sb[tid] = hb1[tid];
    for (int i = tid; i < 16 * DIN; i += 256) {
        int r = i >> 6, d = i & 63;
        int n = n0 + r;
        float v = (d < 32) ? obs[(n & 511) * 32 + d] : lat[n * 32 + (d - 32)];
        sx[r][d] = v;
        g_x[n * DIN + d] = v;
    }
    __syncthreads();

    int r = tid >> 4, cg = tid & 15;
    float acc[8];
#pragma unroll
    for (int c = 0; c < 8; c++) acc[c] = 0.f;
#pragma unroll 8
    for (int d = 0; d < DIN; d++) {
        float a = sx[r][d];
        float4 w0 = *(const float4*)&sw[d][cg * 8];
        float4 w1 = *(const float4*)&sw[d][cg * 8 + 4];
        acc[0] += a * w0.x; acc[1] += a * w0.y;
        acc[2] += a * w0.z; acc[3] += a * w0.w;
        acc[4] += a * w1.x; acc[5] += a * w1.y;
        acc[6] += a * w1.z; acc[7] += a * w1.w;
    }
    int n = n0 + r;
#pragma unroll
    for (int c = 0; c < 8; c++)
        g_h1[n * HID + cg * 8 + c] = fmaxf(acc[c] + sb[cg * 8 + c], 0.f);
}

// ---------------------------------------------------------------------------
// Prep B: Bt[d][n][k] = hw2[k][d*128+n] split into bf16 hi/lo, padded pitch.
// ---------------------------------------------------------------------------
__global__ __launch_bounds__(256) void k_prep_b(const float* __restrict__ hw2) {
    int idx = blockIdx.x * 256 + threadIdx.x;   // 64*16*128 = 131072
    int n = idx & 127, kc = (idx >> 7) & 15, d = idx >> 11;
    int k0 = kc * 8;
    uint32_t hi[4], lo[4];
#pragma unroll
    for (int j = 0; j < 4; j++) {
        float v0 = hw2[(k0 + 2 * j) * 8192 + d * 128 + n];
        float v1 = hw2[(k0 + 2 * j + 1) * 8192 + d * 128 + n];
        uint16_t h0, l0, h1, l1;
        f2hl(v0, h0, l0);
        f2hl(v1, h1, l1);
        hi[j] = (uint32_t)h0 | ((uint32_t)h1 << 16);
        lo[j] = (uint32_t)l0 | ((uint32_t)l1 << 16);
    }
    uint8_t* base = (uint8_t*)g_bbf + d * 67584 + n * 528;
    *(uint4*)(base + k0 * 2) = make_uint4(hi[0], hi[1], hi[2], hi[3]);
    *(uint4*)(base + 256 + k0 * 2) = make_uint4(lo[0], lo[1], lo[2], lo[3]);
}

// ---------------------------------------------------------------------------
// The HMMA hypernet kernel.
// Grid 128 = (64 rowblocks of 128 rows) x (2 d-halves of 32 d's). 256 thr.
// Per d: S[128,128] = H@W_d via bf16 hi/lo mma.sync (3 passes), epilogue
// emb += x[:,d]*relu(S+bias). Partials -> g_embp; combine applies tanh.
// smem: A 128x528B (67584) | SX 128x33 f32 (16896) | BIAS 2x128 f32 (1024)
//       | B dbl-buf 2x67584  => 220672 B
// ---------------------------------------------------------------------------
#define SA_OFF    0
#define SX_OFF    67584
#define SBIAS_OFF 84480
#define SB_OFF    85504
#define HSMEM     220672

__global__ __launch_bounds__(256, 1) void k_hyper_mma(const float* __restrict__ hb2) {
    extern __shared__ __align__(128) uint8_t smem[];
    const uint32_t sbase = smem_u32(smem);
    int tid = threadIdx.x, wid = tid >> 5, lane = tid & 31;
    int rb = blockIdx.x >> 1, dh = blockIdx.x & 1;
    int n0 = rb * 128, d0 = dh * 32;

    // Build A tile (hi/lo bf16, pitch 528B) from g_h1
    __nv_bfloat16* As = (__nv_bfloat16*)(smem + SA_OFF);
    for (int i = tid; i < 128 * 128; i += 256) {
        int r = i >> 7, k = i & 127;
        uint16_t h, l;
        f2hl(g_h1[(n0 + r) * 128 + k], h, l);
        As[r * 264 + k] = __ushort_as_bfloat16(h);
        As[r * 264 + 128 + k] = __ushort_as_bfloat16(l);
    }
    // Stage x
    float* SX = (float*)(smem + SX_OFF);
    for (int i = tid; i < 128 * 32; i += 256) {
        int r = i >> 5, d = i & 31;
        SX[r * 33 + d] = g_x[(n0 + r) * 64 + d0 + d];
    }

    // Prefetch B tile 0 + bias 0
    {
        const uint4* src = &g_bbf[d0 * 4224];
        for (int j = tid; j < 4224; j += 256) cp16(sbase + SB_OFF + j * 16, src + j);
        if (tid < 32) cp16(sbase + SBIAS_OFF + tid * 16, (const uint4*)(hb2 + d0 * 128) + tid);
        CP_COMMIT();
    }

    const int mrow = wid * 16;
    const int r_lo = mrow + (lane >> 2);
    // ldmatrix lane addressing offsets
    const int a_r = mrow + (lane & 15);
    const int a_kadd = (lane >> 4) * 8;
    const int bm = lane >> 3;
    const int b_n = ((bm >> 1) << 3) + (lane & 7);
    const int b_kadd = (bm & 1) * 8;

    float emb[16][4];
#pragma unroll
    for (int j = 0; j < 16; j++)
#pragma unroll
        for (int c = 0; c < 4; c++) emb[j][c] = 0.f;

    for (int i = 0; i < 32; i++) {
        int b = i & 1;
        if (i < 31) {  // prefetch next tile into other buffer
            const uint4* src = &g_bbf[(d0 + i + 1) * 4224];
            uint32_t dst = sbase + SB_OFF + (1 - b) * 67584;
            for (int j = tid; j < 4224; j += 256) cp16(dst + j * 16, src + j);
            if (tid < 32)
                cp16(sbase + SBIAS_OFF + (1 - b) * 512 + tid * 16,
                     (const uint4*)(hb2 + (d0 + i + 1) * 128) + tid);
            CP_COMMIT();
            CP_WAIT(1);
        } else {
            CP_WAIT(0);
        }
        __syncthreads();

        const uint32_t Ab = sbase + SA_OFF;
        const uint32_t Bb = sbase + SB_OFF + b * 67584;
        const float* bias = (const float*)(smem + SBIAS_OFF) + b * 128;
        float xlo = SX[r_lo * 33 + i];
        float xhi = SX[(r_lo + 8) * 33 + i];

#pragma unroll
        for (int nh = 0; nh < 2; nh++) {
            float S[8][4];
#pragma unroll
            for (int t = 0; t < 8; t++)
#pragma unroll
                for (int c = 0; c < 4; c++) S[t][c] = 0.f;

#pragma unroll
            for (int ks = 0; ks < 8; ks++) {
                uint32_t ah[4], al[4];
                int ka = ks * 16 + a_kadd;
                ldsm_x4(ah, Ab + a_r * 528 + ka * 2);
                ldsm_x4(al, Ab + a_r * 528 + (128 + ka) * 2);
#pragma unroll
                for (int g = 0; g < 4; g++) {
                    uint32_t bh[4], bl[4];
                    int nrow = nh * 64 + g * 16 + b_n;
                    int kb = ks * 16 + b_kadd;
                    ldsm_x4(bh, Bb + nrow * 528 + kb * 2);
                    ldsm_x4(bl, Bb + nrow * 528 + (128 + kb) * 2);
                    mma16816(S[2 * g], ah, bh[0], bh[1]);
                    mma16816(S[2 * g], al, bh[0], bh[1]);
                    mma16816(S[2 * g], ah, bl[0], bl[1]);
                    mma16816(S[2 * g + 1], ah, bh[2], bh[3]);
                    mma16816(S[2 * g + 1], al, bh[2], bh[3]);
                    mma16816(S[2 * g + 1], ah, bl[2], bl[3]);
                }
            }
            // fold into emb
#pragma unroll
            for (int t = 0; t < 8; t++) {
                int col = nh * 64 + t * 8 + (lane & 3) * 2;
                float2 bv = *(const float2*)&bias[col];
                float* e = emb[nh * 8 + t];
                e[0] += xlo * fmaxf(S[t][0] + bv.x, 0.f);
                e[1] += xlo * fmaxf(S[t][1] + bv.y, 0.f);
                e[2] += xhi * fmaxf(S[t][2] + bv.x, 0.f);
                e[3] += xhi * fmaxf(S[t][3] + bv.y, 0.f);
            }
        }
        __syncthreads();
    }

    // store partial sums
    float* dst = g_embp + dh * (NTOT * HID) + n0 * 128;
#pragma unroll
    for (int j = 0; j < 16; j++) {
        int col = (j >> 3) * 64 + (j & 7) * 8 + (lane & 3) * 2;
        *(float2*)&dst[r_lo * 128 + col] = make_float2(emb[j][0], emb[j][1]);
        *(float2*)&dst[(r_lo + 8) * 128 + col] = make_float2(emb[j][2], emb[j][3]);
    }
}

__global__ __launch_bounds__(256) void k_combine() {
    int idx = blockIdx.x * 256 + threadIdx.x;
    g_emb[idx] = tanhf(g_embp[idx] + g_embp[NTOT * HID + idx]);
}

// ---------------------------------------------------------------------------
// Generic fused linear (SIMT, unchanged)
// ---------------------------------------------------------------------------
template <bool CONCAT>
__global__ __launch_bounds__(256) void k_mlp(
    const float* __restrict__ A, const float* __restrict__ A2,
    const float* __restrict__ W, const float* __restrict__ bias,
    float* __restrict__ out, int K, int do_relu) {
    __shared__ __align__(16) float As[32][68];
    __shared__ __align__(16) float Ws[32][HID];
    int tid = threadIdx.x;
    int n0 = blockIdx.x * 64;
    int tr = tid >> 4, tc = tid & 15;

    float acc[4][8];
#pragma unroll
    for (int a = 0; a < 4; a++)
#pragma unroll
        for (int b = 0; b < 8; b++) acc[a][b] = 0.f;

    int nkc = K >> 5;
    for (int kc = 0; kc < nkc; kc++) {
        __syncthreads();
        for (int i = tid; i < 64 * 32; i += 256) {
            int row = i >> 5, kk = i & 31;
            int n = n0 + row;
            int kg = kc * 32 + kk;
            float v;
            if (CONCAT)
                v = (kg < HID) ? A[n * HID + kg] : A2[(n & 511) * HID + (kg - HID)];
            else
                v = A[n * K + kg];
            As[kk][row] = v;
        }
        for (int i = tid; i < 32 * HID; i += 256) {
            int kk = i >> 7, c = i & 127;
            Ws[kk][c] = W[(kc * 32 + kk) * HID + c];
        }
        __syncthreads();
#pragma unroll
        for (int k = 0; k < 32; k++) {
            float4 av4 = *(const float4*)&As[k][tr * 4];
            float4 b0 = *(const float4*)&Ws[k][tc * 8];
            float4 b1 = *(const float4*)&Ws[k][tc * 8 + 4];
            float a_[4] = {av4.x, av4.y, av4.z, av4.w};
            float b_[8] = {b0.x, b0.y, b0.z, b0.w, b1.x, b1.y, b1.z, b1.w};
#pragma unroll
            for (int rr = 0; rr < 4; rr++)
#pragma unroll
                for (int cc = 0; cc < 8; cc++)
                    acc[rr][cc] += a_[rr] * b_[cc];
        }
    }
#pragma unroll
    for (int rr = 0; rr < 4; rr++) {
        int n = n0 + tr * 4 + rr;
#pragma unroll
        for (int cc = 0; cc < 8; cc++) {
            float v = acc[rr][cc] + bias[tc * 8 + cc];
            if (do_relu) v = fmaxf(v, 0.f);
            out[n * HID + tc * 8 + cc] = v;
        }
    }
}

__global__ void k_mean() {
    int idx = blockIdx.x * 256 + threadIdx.x;
    int b = idx >> 7, h = idx & 127;
    float s = 0.f;
#pragma unroll
    for (int a = 0; a < NADV; a++) s += g_emb[((b << 4) + a) * HID + h];
    g_mean[idx] = s * (1.f / 16.f);
}

__global__ void k_score(const float* __restrict__ A,
                        const float* __restrict__ w,
                        const float* __restrict__ b) {
    int warp = threadIdx.x >> 5, lane = threadIdx.x & 31;
    int n = blockIdx.x * 8 + warp;
    float s = 0.f;
#pragma unroll
    for (int k = lane; k < HID; k += 32) s += A[n * HID + k] * w[k];
#pragma unroll
    for (int off = 16; off; off >>= 1) s += __shfl_xor_sync(0xffffffffu, s, off);
    if (lane == 0) g_sc[n] = s + b[0];
}

__global__ void k_final(float* __restrict__ out) {
    __shared__ float sc[NADV];
    int b = blockIdx.x, tid = threadIdx.x;
    if (tid < NADV) sc[tid] = g_sc[b * NADV + tid];
    __syncthreads();
    float m = sc[0];
#pragma unroll
    for (int a = 1; a < NADV; a++) m = fmaxf(m, sc[a]);
    float den = 0.f, o = 0.f;
#pragma unroll
    for (int a = 0; a < NADV; a++) {
        float e = expf(sc[a] - m);
        den += e;
        o += e * g_vals[(b * NADV + a) * HID + tid];
    }
    out[b * HID + tid] = o / den;
}

// ---------------------------------------------------------------------------
extern "C" void kernel_launch(void* const* d_in, const int* in_sizes, int n_in,
                              void* d_out, int out_size) {
    const float* obs = (const float*)d_in[0];
    const float* lat = (const float*)d_in[1];
    const float* hw1 = (const float*)d_in[2];
    const float* hb1 = (const float*)d_in[3];
    const float* hw2 = (const float*)d_in[4];
    const float* hb2 = (const float*)d_in[5];
    const float* vw1 = (const float*)d_in[6];
    const float* vb1 = (const float*)d_in[7];
    const float* vw2 = (const float*)d_in[8];
    const float* vb2 = (const float*)d_in[9];
    const float* aw1 = (const float*)d_in[10];
    const float* ab1 = (const float*)d_in[11];
    const float* aw2 = (const float*)d_in[12];
    const float* ab2 = (const float*)d_in[13];
    const float* aw3 = (const float*)d_in[14];
    const float* ab3 = (const float*)d_in[15];
    float* out = (float*)d_out;

    static int smem_set = 0;
    if (!smem_set) {
        cudaFuncSetAttribute(k_hyper_mma, cudaFuncAttributeMaxDynamicSharedMemorySize, HSMEM);
        smem_set = 1;
    }

    float *p_emb, *p_vh, *p_vals, *p_mean, *p_a1, *p_a2;
    cudaGetSymbolAddress((void**)&p_emb, g_emb);
    cudaGetSymbolAddress((void**)&p_vh, g_vh);
    cudaGetSymbolAddress((void**)&p_vals, g_vals);
    cudaGetSymbolAddress((void**)&p_mean, g_mean);
    cudaGetSymbolAddress((void**)&p_a1, g_a1);
    cudaGetSymbolAddress((void**)&p_a2, g_a2);

    k_build_h1<<<NTOT / 16, 256>>>(obs, lat, hw1, hb1);
    k_prep_b<<<512, 256>>>(hw2);
    k_hyper_mma<<<128, 256, HSMEM>>>(hb2);
    k_combine<<<NTOT * HID / 256, 256>>>();
    k_mlp<false><<<NTOT / 64, 256>>>(p_emb, nullptr, vw1, vb1, p_vh, 128, 1);
    k_mlp<false><<<NTOT / 64, 256>>>(p_vh, nullptr, vw2, vb2, p_vals, 128, 1);
    k_mean<<<(BATCH * HID) / 256, 256>>>();
    k_mlp<true><<<NTOT / 64, 256>>>(p_emb, p_mean, aw1, ab1, p_a1, 256, 1);
    k_mlp<false><<<NTOT / 64, 256>>>(p_a1, nullptr, aw2, ab2, p_a2, 128, 1);
    k_score<<<NTOT / 8, 256>>>(p_a2, aw3, ab3);
    k_final<<<BATCH, HID>>>(out);
}

// round 4
// speedup vs baseline: 3.4833x; 1.0315x over previous
#include <cuda_runtime.h>
#include <cuda_bf16.h>
#include <math.h>
#include <stdint.h>

// Problem constants
#define NTOT 8192   // B * A
#define BATCH 512
#define NADV 16
#define DIN 64      // DS + DO
#define HID 128

// Scratch
__device__ float g_x[NTOT * DIN];
__device__ float g_h1[NTOT * HID];
__device__ float g_emb[NTOT * HID];
__device__ float g_embp[2 * NTOT * HID];   // partial einsum sums (pre-tanh)
__device__ float g_vals[NTOT * HID];
__device__ float g_mean[BATCH * HID];
__device__ float g_sc[NTOT];
// Pre-converted tiles, bf16 hi/lo, row pitch 528B (264 bf16: hi 0..127, lo 128..255, 8 pad)
// one tile = 128 rows x 528B = 67584B = 4224 uint4
__device__ uint4 g_abf[64 * 4224];   // A tiles per rowblock
__device__ uint4 g_bbf[64 * 4224];   // B tiles per d

// ---------------------------------------------------------------------------
// helpers
// ---------------------------------------------------------------------------
__device__ __forceinline__ uint32_t smem_u32(const void* p) {
    uint32_t a;
    asm("{ .reg .u64 t; cvta.to.shared.u64 t, %1; cvt.u32.u64 %0, t; }" : "=r"(a) : "l"(p));
    return a;
}
__device__ __forceinline__ void f2hl(float v, uint16_t& h, uint16_t& l) {
    __nv_bfloat16 bh = __float2bfloat16_rn(v);
    float r = v - __bfloat162float(bh);
    __nv_bfloat16 bl = __float2bfloat16_rn(r);
    h = __bfloat16_as_ushort(bh);
    l = __bfloat16_as_ushort(bl);
}
__device__ __forceinline__ void ldsm_x4(uint32_t* r, uint32_t addr) {
    asm volatile("ldmatrix.sync.aligned.m8n8.x4.shared.b16 {%0,%1,%2,%3}, [%4];"
                 : "=r"(r[0]), "=r"(r[1]), "=r"(r[2]), "=r"(r[3]) : "r"(addr));
}
__device__ __forceinline__ void mma16816(float* d, const uint32_t* a, uint32_t b0, uint32_t b1) {
    asm volatile(
        "mma.sync.aligned.m16n8k16.row.col.f32.bf16.bf16.f32 "
        "{%0,%1,%2,%3}, {%4,%5,%6,%7}, {%8,%9}, {%0,%1,%2,%3};"
        : "+f"(d[0]), "+f"(d[1]), "+f"(d[2]), "+f"(d[3])
        : "r"(a[0]), "r"(a[1]), "r"(a[2]), "r"(a[3]), "r"(b0), "r"(b1));
}
__device__ __forceinline__ void cp16(uint32_t dst, const void* src) {
    asm volatile("cp.async.cg.shared.global [%0], [%1], 16;" :: "r"(dst), "l"(src) : "memory");
}
#define CP_COMMIT() asm volatile("cp.async.commit_group;" ::: "memory")
#define CP_WAIT(N)  asm volatile("cp.async.wait_group %0;" :: "n"(N) : "memory")

// ---------------------------------------------------------------------------
// Kernel 0: build mlp_input and h1 = relu(x @ hw1 + hb1)
// ---------------------------------------------------------------------------
__global__ __launch_bounds__(256) void k_build_h1(
    const float* __restrict__ obs, const float* __restrict__ lat,
    const float* __restrict__ hw1, const float* __restrict__ hb1) {
    __shared__ __align__(16) float sw[DIN][HID];
    __shared__ float sb[HID];
    __shared__ float sx[16][DIN];
    int tid = threadIdx.x;
    int n0 = blockIdx.x * 16;

    for (int i = tid; i < DIN * HID; i += 256) ((float*)sw)[i] = hw1[i];
    if (tid < HID) sb[tid] = hb1[tid];
    for (int i = tid; i < 16 * DIN; i += 256) {
        int r = i >> 6, d = i & 63;
        int n = n0 + r;
        float v = (d < 32) ? obs[(n & 511) * 32 + d] : lat[n * 32 + (d - 32)];
        sx[r][d] = v;
        g_x[n * DIN + d] = v;
    }
    __syncthreads();

    int r = tid >> 4, cg = tid & 15;
    float acc[8];
#pragma unroll
    for (int c = 0; c < 8; c++) acc[c] = 0.f;
#pragma unroll 8
    for (int d = 0; d < DIN; d++) {
        float a = sx[r][d];
        float4 w0 = *(const float4*)&sw[d][cg * 8];
        float4 w1 = *(const float4*)&sw[d][cg * 8 + 4];
        acc[0] += a * w0.x; acc[1] += a * w0.y;
        acc[2] += a * w0.z; acc[3] += a * w0.w;
        acc[4] += a * w1.x; acc[5] += a * w1.y;
        acc[6] += a * w1.z; acc[7] += a * w1.w;
    }
    int n = n0 + r;
#pragma unroll
    for (int c = 0; c < 8; c++)
        g_h1[n * HID + cg * 8 + c] = fmaxf(acc[c] + sb[cg * 8 + c], 0.f);
}

// ---------------------------------------------------------------------------
// Kernel 1: prep B tiles  (Bt[d][n][k] = hw2[k][d*128+n] hi/lo)
// ---------------------------------------------------------------------------
__global__ __launch_bounds__(256) void k_prep_b(const float* __restrict__ hw2) {
    int idx = blockIdx.x * 256 + threadIdx.x;   // 131072
    int n = idx & 127, kc = (idx >> 7) & 15, d = idx >> 11;
    int k0 = kc * 8;
    uint32_t hi[4], lo[4];
#pragma unroll
    for (int j = 0; j < 4; j++) {
        float v0 = hw2[(k0 + 2 * j) * 8192 + d * 128 + n];
        float v1 = hw2[(k0 + 2 * j + 1) * 8192 + d * 128 + n];
        uint16_t h0, l0, h1, l1;
        f2hl(v0, h0, l0);
        f2hl(v1, h1, l1);
        hi[j] = (uint32_t)h0 | ((uint32_t)h1 << 16);
        lo[j] = (uint32_t)l0 | ((uint32_t)l1 << 16);
    }
    uint8_t* base = (uint8_t*)g_bbf + d * 67584 + n * 528;
    *(uint4*)(base + k0 * 2) = make_uint4(hi[0], hi[1], hi[2], hi[3]);
    *(uint4*)(base + 256 + k0 * 2) = make_uint4(lo[0], lo[1], lo[2], lo[3]);
}

// ---------------------------------------------------------------------------
// Kernel 2: prep A tiles from g_h1 (hi/lo split, same pitched layout)
// ---------------------------------------------------------------------------
__global__ __launch_bounds__(256) void k_prep_a() {
    int idx = blockIdx.x * 256 + threadIdx.x;   // 131072
    int row = idx >> 4, k0 = (idx & 15) * 8;
    uint32_t hi[4], lo[4];
#pragma unroll
    for (int j = 0; j < 4; j++) {
        float v0 = g_h1[row * 128 + k0 + 2 * j];
        float v1 = g_h1[row * 128 + k0 + 2 * j + 1];
        uint16_t h0, l0, h1, l1;
        f2hl(v0, h0, l0);
        f2hl(v1, h1, l1);
        hi[j] = (uint32_t)h0 | ((uint32_t)h1 << 16);
        lo[j] = (uint32_t)l0 | ((uint32_t)l1 << 16);
    }
    uint8_t* base = (uint8_t*)g_abf + (row >> 7) * 67584 + (row & 127) * 528;
    *(uint4*)(base + k0 * 2) = make_uint4(hi[0], hi[1], hi[2], hi[3]);
    *(uint4*)(base + 256 + k0 * 2) = make_uint4(lo[0], lo[1], lo[2], lo[3]);
}

// ---------------------------------------------------------------------------
// Kernel 3: HMMA hypernet. Grid 128 = 64 rowblocks x 2 d-halves, 256 thr.
// ---------------------------------------------------------------------------
#define SA_OFF    0
#define SX_OFF    67584
#define SBIAS_OFF 84480
#define SB_OFF    85504
#define HSMEM     220672

__global__ __launch_bounds__(256, 1) void k_hyper_mma(const float* __restrict__ hb2) {
    extern __shared__ __align__(128) uint8_t smem[];
    const uint32_t sbase = smem_u32(smem);
    int tid = threadIdx.x, wid = tid >> 5, lane = tid & 31;
    int rb = blockIdx.x >> 1, dh = blockIdx.x & 1;
    int n0 = rb * 128, d0 = dh * 32;

    // Prefetch A tile + B tile 0 + bias 0 (one cp.async group)
    {
        const uint4* asrc = &g_abf[rb * 4224];
        for (int j = tid; j < 4224; j += 256) cp16(sbase + SA_OFF + j * 16, asrc + j);
        const uint4* bsrc = &g_bbf[d0 * 4224];
        for (int j = tid; j < 4224; j += 256) cp16(sbase + SB_OFF + j * 16, bsrc + j);
        if (tid < 32) cp16(sbase + SBIAS_OFF + tid * 16, (const uint4*)(hb2 + d0 * 128) + tid);
        CP_COMMIT();
    }
    // Stage x
    float* SX = (float*)(smem + SX_OFF);
    for (int i = tid; i < 128 * 32; i += 256) {
        int r = i >> 5, d = i & 31;
        SX[r * 33 + d] = g_x[(n0 + r) * 64 + d0 + d];
    }

    const int mrow = wid * 16;
    const int r_lo = mrow + (lane >> 2);
    const int a_r = mrow + (lane & 15);
    const int a_kadd = (lane >> 4) * 8;
    const int bm = lane >> 3;
    const int b_n = ((bm >> 1) << 3) + (lane & 7);
    const int b_kadd = (bm & 1) * 8;

    float emb[16][4];
#pragma unroll
    for (int j = 0; j < 16; j++)
#pragma unroll
        for (int c = 0; c < 4; c++) emb[j][c] = 0.f;

    for (int i = 0; i < 32; i++) {
        int b = i & 1;
        if (i < 31) {
            const uint4* src = &g_bbf[(d0 + i + 1) * 4224];
            uint32_t dst = sbase + SB_OFF + (1 - b) * 67584;
            for (int j = tid; j < 4224; j += 256) cp16(dst + j * 16, src + j);
            if (tid < 32)
                cp16(sbase + SBIAS_OFF + (1 - b) * 512 + tid * 16,
                     (const uint4*)(hb2 + (d0 + i + 1) * 128) + tid);
            CP_COMMIT();
            CP_WAIT(1);
        } else {
            CP_WAIT(0);
        }
        __syncthreads();

        const uint32_t Ab = sbase + SA_OFF;
        const uint32_t Bb = sbase + SB_OFF + b * 67584;
        const float* bias = (const float*)(smem + SBIAS_OFF) + b * 128;
        float xlo = SX[r_lo * 33 + i];
        float xhi = SX[(r_lo + 8) * 33 + i];

#pragma unroll
        for (int nh = 0; nh < 2; nh++) {
            float S[8][4];
#pragma unroll
            for (int t = 0; t < 8; t++)
#pragma unroll
                for (int c = 0; c < 4; c++) S[t][c] = 0.f;

#pragma unroll
            for (int ks = 0; ks < 8; ks++) {
                uint32_t ah[4], al[4];
                int ka = ks * 16 + a_kadd;
                ldsm_x4(ah, Ab + a_r * 528 + ka * 2);
                ldsm_x4(al, Ab + a_r * 528 + (128 + ka) * 2);
#pragma unroll
                for (int g = 0; g < 4; g++) {
                    uint32_t bh[4], bl[4];
                    int nrow = nh * 64 + g * 16 + b_n;
                    int kb = ks * 16 + b_kadd;
                    ldsm_x4(bh, Bb + nrow * 528 + kb * 2);
                    ldsm_x4(bl, Bb + nrow * 528 + (128 + kb) * 2);
                    mma16816(S[2 * g], ah, bh[0], bh[1]);
                    mma16816(S[2 * g], al, bh[0], bh[1]);
                    mma16816(S[2 * g], ah, bl[0], bl[1]);
                    mma16816(S[2 * g + 1], ah, bh[2], bh[3]);
                    mma16816(S[2 * g + 1], al, bh[2], bh[3]);
                    mma16816(S[2 * g + 1], ah, bl[2], bl[3]);
                }
            }
#pragma unroll
            for (int t = 0; t < 8; t++) {
                int col = nh * 64 + t * 8 + (lane & 3) * 2;
                float2 bv = *(const float2*)&bias[col];
                float* e = emb[nh * 8 + t];
                e[0] += xlo * fmaxf(S[t][0] + bv.x, 0.f);
                e[1] += xlo * fmaxf(S[t][1] + bv.y, 0.f);
                e[2] += xhi * fmaxf(S[t][2] + bv.x, 0.f);
                e[3] += xhi * fmaxf(S[t][3] + bv.y, 0.f);
            }
        }
        __syncthreads();
    }

    float* dst = g_embp + dh * (NTOT * HID) + n0 * 128;
#pragma unroll
    for (int j = 0; j < 16; j++) {
        int col = (j >> 3) * 64 + (j & 7) * 8 + (lane & 3) * 2;
        *(float2*)&dst[r_lo * 128 + col] = make_float2(emb[j][0], emb[j][1]);
        *(float2*)&dst[(r_lo + 8) * 128 + col] = make_float2(emb[j][2], emb[j][3]);
    }
}

// ---------------------------------------------------------------------------
// Kernel 4: combine partials (tanh) + per-batch mean. One CTA per batch.
// ---------------------------------------------------------------------------
__global__ __launch_bounds__(256) void k_combine_mean() {
    __shared__ float red[2][128];
    int b = blockIdx.x, tid = threadIdx.x;
    int col = tid & 127, half = tid >> 7;
    float s = 0.f;
#pragma unroll
    for (int j = 0; j < 8; j++) {
        int n = b * 16 + half * 8 + j;
        float v = tanhf(g_embp[n * 128 + col] + g_embp[NTOT * HID + n * 128 + col]);
        g_emb[n * 128 + col] = v;
        s += v;
    }
    red[half][col] = s;
    __syncthreads();
    if (half == 0) g_mean[b * 128 + col] = (red[0][col] + red[1][col]) * (1.f / 16.f);
}

// ---------------------------------------------------------------------------
// Fused tail GEMM helper: 32 rows x 128 cols, 256 threads, 2x8 per thread.
// sA: [k][row] pitch 33; sW: [k][col] pitch 128.
// ---------------------------------------------------------------------------
__device__ __forceinline__ void gemm32(const float* __restrict__ sA,
                                       const float* __restrict__ sW,
                                       int tid, float acc[2][8]) {
    int tr = tid >> 4, tc = tid & 15;
    const float* ap = sA + tr * 2;
    const float* wp = sW + tc * 8;
#pragma unroll 4
    for (int k = 0; k < 128; k++) {
        float a0 = ap[k * 33], a1 = ap[k * 33 + 1];
        float4 w0 = *(const float4*)(wp + k * 128);
        float4 w1 = *(const float4*)(wp + k * 128 + 4);
        acc[0][0] += a0 * w0.x; acc[0][1] += a0 * w0.y;
        acc[0][2] += a0 * w0.z; acc[0][3] += a0 * w0.w;
        acc[0][4] += a0 * w1.x; acc[0][5] += a0 * w1.y;
        acc[0][6] += a0 * w1.z; acc[0][7] += a0 * w1.w;
        acc[1][0] += a1 * w0.x; acc[1][1] += a1 * w0.y;
        acc[1][2] += a1 * w0.z; acc[1][3] += a1 * w0.w;
        acc[1][4] += a1 * w1.x; acc[1][5] += a1 * w1.y;
        acc[1][6] += a1 * w1.z; acc[1][7] += a1 * w1.w;
    }
}

// smem layout for fused tail kernels (floats): sA 4224 | sH 4224 | sW 16384 | sb 128 | sw3 128
#define TA 0
#define TH 4224
#define TW 8448
#define TBIAS 24832
#define TW3 24960
#define TSMEM ((24960 + 128) * 4)

// ---------------------------------------------------------------------------
// Kernel 5: value MLP, two fused layers. Grid 256 (32 rows/CTA).
// ---------------------------------------------------------------------------
__global__ __launch_bounds__(256, 2) void k_val2(
    const float* __restrict__ W1, const float* __restrict__ b1,
    const float* __restrict__ W2, const float* __restrict__ b2) {
    extern __shared__ __align__(16) float sm[];
    float* sA = sm + TA;
    float* sH = sm + TH;
    float* sW = sm + TW;
    float* sb = sm + TBIAS;
    int tid = threadIdx.x, n0 = blockIdx.x * 32;
    int tr = tid >> 4, tc = tid & 15;

    // W1 + b1 via cp.async
    for (int i = tid; i < 4096; i += 256) cp16(smem_u32(sW) + i * 16, (const uint4*)W1 + i);
    if (tid < 32) cp16(smem_u32(sb) + tid * 16, (const uint4*)b1 + tid);
    CP_COMMIT();
    // A = emb rows, transposed
    for (int i = tid; i < 4096; i += 256) {
        int r = i >> 7, k = i & 127;
        sA[k * 33 + r] = g_emb[(n0 + r) * 128 + k];
    }
    CP_WAIT(0);
    __syncthreads();

    float acc[2][8];
#pragma unroll
    for (int r = 0; r < 2; r++)
#pragma unroll
        for (int c = 0; c < 8; c++) acc[r][c] = 0.f;
    gemm32(sA, sW, tid, acc);
#pragma unroll
    for (int r = 0; r < 2; r++)
#pragma unroll
        for (int c = 0; c < 8; c++)
            sH[(tc * 8 + c) * 33 + tr * 2 + r] = fmaxf(acc[r][c] + sb[tc * 8 + c], 0.f);
    __syncthreads();

    // W2 + b2
    for (int i = tid; i < 4096; i += 256) cp16(smem_u32(sW) + i * 16, (const uint4*)W2 + i);
    if (tid < 32) cp16(smem_u32(sb) + tid * 16, (const uint4*)b2 + tid);
    CP_COMMIT();
    CP_WAIT(0);
    __syncthreads();

#pragma unroll
    for (int r = 0; r < 2; r++)
#pragma unroll
        for (int c = 0; c < 8; c++) acc[r][c] = 0.f;
    gemm32(sH, sW, tid, acc);
#pragma unroll
    for (int r = 0; r < 2; r++) {
        int n = n0 + tr * 2 + r;
        float4 o0 = make_float4(fmaxf(acc[r][0] + sb[tc * 8 + 0], 0.f),
                                fmaxf(acc[r][1] + sb[tc * 8 + 1], 0.f),
                                fmaxf(acc[r][2] + sb[tc * 8 + 2], 0.f),
                                fmaxf(acc[r][3] + sb[tc * 8 + 3], 0.f));
        float4 o1 = make_float4(fmaxf(acc[r][4] + sb[tc * 8 + 4], 0.f),
                                fmaxf(acc[r][5] + sb[tc * 8 + 5], 0.f),
                                fmaxf(acc[r][6] + sb[tc * 8 + 6], 0.f),
                                fmaxf(acc[r][7] + sb[tc * 8 + 7], 0.f));
        *(float4*)&g_vals[n * 128 + tc * 8] = o0;
        *(float4*)&g_vals[n * 128 + tc * 8 + 4] = o1;
    }
}

// ---------------------------------------------------------------------------
// Kernel 6: attention MLP (K=256 layer, 128 layer, score). Grid 256.
// ---------------------------------------------------------------------------
__global__ __launch_bounds__(256, 2) void k_att(
    const float* __restrict__ W1, const float* __restrict__ b1,
    const float* __restrict__ W2, const float* __restrict__ b2,
    const float* __restrict__ w3, const float* __restrict__ b3) {
    extern __shared__ __align__(16) float sm[];
    float* sA = sm + TA;
    float* sH = sm + TH;
    float* sW = sm + TW;
    float* sb = sm + TBIAS;
    float* sw3 = sm + TW3;
    int tid = threadIdx.x, n0 = blockIdx.x * 32;
    int tr = tid >> 4, tc = tid & 15;

    // chunk 0: W1 rows 0..127 (emb part)
    for (int i = tid; i < 4096; i += 256) cp16(smem_u32(sW) + i * 16, (const uint4*)W1 + i);
    if (tid < 32) cp16(smem_u32(sb) + tid * 16, (const uint4*)b1 + tid);
    CP_COMMIT();
    for (int i = tid; i < 4096; i += 256) {
        int r = i >> 7, k = i & 127;
        sA[k * 33 + r] = g_emb[(n0 + r) * 128 + k];
    }
    CP_WAIT(0);
    __syncthreads();

    float acc[2][8];
#pragma unroll
    for (int r = 0; r < 2; r++)
#pragma unroll
        for (int c = 0; c < 8; c++) acc[r][c] = 0.f;
    gemm32(sA, sW, tid, acc);
    __syncthreads();

    // chunk 1: W1 rows 128..255 (mean part); A = mean[(n)%512]
    for (int i = tid; i < 4096; i += 256) cp16(smem_u32(sW) + i * 16, (const uint4*)W1 + 4096 + i);
    CP_COMMIT();
    for (int i = tid; i < 4096; i += 256) {
        int r = i >> 7, k = i & 127;
        sA[k * 33 + r] = g_mean[((n0 + r) & 511) * 128 + k];
    }
    CP_WAIT(0);
    __syncthreads();
    gemm32(sA, sW, tid, acc);
#pragma unroll
    for (int r = 0; r < 2; r++)
#pragma unroll
        for (int c = 0; c < 8; c++)
            sH[(tc * 8 + c) * 33 + tr * 2 + r] = fmaxf(acc[r][c] + sb[tc * 8 + c], 0.f);
    __syncthreads();

    // layer 2 (aw2) + stage w3
    for (int i = tid; i < 4096; i += 256) cp16(smem_u32(sW) + i * 16, (const uint4*)W2 + i);
    if (tid < 32) cp16(smem_u32(sb) + tid * 16, (const uint4*)b2 + tid);
    if (tid >= 32 && tid < 64) cp16(smem_u32(sw3) + (tid - 32) * 16, (const uint4*)w3 + (tid - 32));
    CP_COMMIT();
    CP_WAIT(0);
    __syncthreads();

#pragma unroll
    for (int r = 0; r < 2; r++)
#pragma unroll
        for (int c = 0; c < 8; c++) acc[r][c] = 0.f;
    gemm32(sH, sW, tid, acc);
#pragma unroll
    for (int r = 0; r < 2; r++)
#pragma unroll
        for (int c = 0; c < 8; c++)
            sA[(tc * 8 + c) * 33 + tr * 2 + r] = fmaxf(acc[r][c] + sb[tc * 8 + c], 0.f);
    __syncthreads();

    // score: sc[row] = dot(a2[row,:], w3) + b3
    int row = tid >> 3, l8 = tid & 7;
    float s = 0.f;
#pragma unroll
    for (int k = l8; k < 128; k += 8) s += sA[k * 33 + row] * sw3[k];
    s += __shfl_xor_sync(0xffffffffu, s, 1);
    s += __shfl_xor_sync(0xffffffffu, s, 2);
    s += __shfl_xor_sync(0xffffffffu, s, 4);
    if (l8 == 0) g_sc[n0 + row] = s + b3[0];
}

// ---------------------------------------------------------------------------
// Kernel 7: softmax over 16 + weighted sum -> out[512,128]
// ---------------------------------------------------------------------------
__global__ void k_final(float* __restrict__ out) {
    __shared__ float sc[NADV];
    int b = blockIdx.x, tid = threadIdx.x;
    if (tid < NADV) sc[tid] = g_sc[b * NADV + tid];
    __syncthreads();
    float m = sc[0];
#pragma unroll
    for (int a = 1; a < NADV; a++) m = fmaxf(m, sc[a]);
    float den = 0.f, o = 0.f;
#pragma unroll
    for (int a = 0; a < NADV; a++) {
        float e = expf(sc[a] - m);
        den += e;
        o += e * g_vals[(b * NADV + a) * HID + tid];
    }
    out[b * HID + tid] = o / den;
}

// ---------------------------------------------------------------------------
extern "C" void kernel_launch(void* const* d_in, const int* in_sizes, int n_in,
                              void* d_out, int out_size) {
    const float* obs = (const float*)d_in[0];
    const float* lat = (const float*)d_in[1];
    const float* hw1 = (const float*)d_in[2];
    const float* hb1 = (const float*)d_in[3];
    const float* hw2 = (const float*)d_in[4];
    const float* hb2 = (const float*)d_in[5];
    const float* vw1 = (const float*)d_in[6];
    const float* vb1 = (const float*)d_in[7];
    const float* vw2 = (const float*)d_in[8];
    const float* vb2 = (const float*)d_in[9];
    const float* aw1 = (const float*)d_in[10];
    const float* ab1 = (const float*)d_in[11];
    const float* aw2 = (const float*)d_in[12];
    const float* ab2 = (const float*)d_in[13];
    const float* aw3 = (const float*)d_in[14];
    const float* ab3 = (const float*)d_in[15];
    float* out = (float*)d_out;

    static int attr_set = 0;
    if (!attr_set) {
        cudaFuncSetAttribute(k_hyper_mma, cudaFuncAttributeMaxDynamicSharedMemorySize, HSMEM);
        cudaFuncSetAttribute(k_val2, cudaFuncAttributeMaxDynamicSharedMemorySize, TSMEM);
        cudaFuncSetAttribute(k_att, cudaFuncAttributeMaxDynamicSharedMemorySize, TSMEM);
        attr_set = 1;
    }

    k_build_h1<<<NTOT / 16, 256>>>(obs, lat, hw1, hb1);      // 0
    k_prep_b<<<512, 256>>>(hw2);                             // 1
    k_prep_a<<<512, 256>>>();                                // 2
    k_hyper_mma<<<128, 256, HSMEM>>>(hb2);                   // 3 (ncu capture slot)
    k_combine_mean<<<BATCH, 256>>>();                        // 4
    k_val2<<<NTOT / 32, 256, TSMEM>>>(vw1, vb1, vw2, vb2);   // 5
    k_att<<<NTOT / 32, 256, TSMEM>>>(aw1, ab1, aw2, ab2, aw3, ab3);  // 6
    k_final<<<BATCH, HID>>>(out);                            // 7
}

// round 5
// speedup vs baseline: 4.0892x; 1.1739x over previous
#include <cuda_runtime.h>
#include <cuda_fp16.h>
#include <math.h>
#include <stdint.h>

// Problem constants
#define NTOT 8192   // B * A
#define BATCH 512
#define NADV 16
#define DIN 64      // DS + DO
#define HID 128

// Scratch
__device__ float g_x[NTOT * DIN];
__device__ float g_emb[NTOT * HID];
__device__ float g_embp[2 * NTOT * HID];   // partial einsum sums (pre-tanh)
__device__ float g_vals[NTOT * HID];
__device__ float g_mean[BATCH * HID];
__device__ float g_sc[NTOT];
// A tiles: fp16 hi/lo, row pitch 528B (264 halves: hi 0..127, lo 128..255, 8 pad)
// one tile = 128 rows x 528B = 67584B = 4224 uint4; 64 rowblock tiles
__device__ uint4 g_abf[64 * 4224];
// B tiles: fp16 hi only, row pitch 272B (136 halves: hi 0..127, 8 pad)
// one tile = 128 rows x 272B = 34816B = 2176 uint4; 64 d tiles
__device__ uint4 g_bbf[64 * 2176];

// ---------------------------------------------------------------------------
// helpers
// ---------------------------------------------------------------------------
__device__ __forceinline__ uint32_t smem_u32(const void* p) {
    uint32_t a;
    asm("{ .reg .u64 t; cvta.to.shared.u64 t, %1; cvt.u32.u64 %0, t; }" : "=r"(a) : "l"(p));
    return a;
}
__device__ __forceinline__ void f2hl16(float v, uint16_t& h, uint16_t& l) {
    __half hh = __float2half_rn(v);
    float r = v - __half2float(hh);
    __half hl = __float2half_rn(r);
    h = __half_as_ushort(hh);
    l = __half_as_ushort(hl);
}
__device__ __forceinline__ void ldsm_x4(uint32_t* r, uint32_t addr) {
    asm volatile("ldmatrix.sync.aligned.m8n8.x4.shared.b16 {%0,%1,%2,%3}, [%4];"
                 : "=r"(r[0]), "=r"(r[1]), "=r"(r[2]), "=r"(r[3]) : "r"(addr));
}
__device__ __forceinline__ void mma16816h(float* d, const uint32_t* a, uint32_t b0, uint32_t b1) {
    asm volatile(
        "mma.sync.aligned.m16n8k16.row.col.f32.f16.f16.f32 "
        "{%0,%1,%2,%3}, {%4,%5,%6,%7}, {%8,%9}, {%0,%1,%2,%3};"
        : "+f"(d[0]), "+f"(d[1]), "+f"(d[2]), "+f"(d[3])
        : "r"(a[0]), "r"(a[1]), "r"(a[2]), "r"(a[3]), "r"(b0), "r"(b1));
}
__device__ __forceinline__ void cp16(uint32_t dst, const void* src) {
    asm volatile("cp.async.cg.shared.global [%0], [%1], 16;" :: "r"(dst), "l"(src) : "memory");
}
#define CP_COMMIT() asm volatile("cp.async.commit_group;" ::: "memory")
#define CP_WAIT(N)  asm volatile("cp.async.wait_group %0;" :: "n"(N) : "memory")

// ---------------------------------------------------------------------------
// Kernel 0 (fused): blocks 0..511 build h1 rows -> fp16 hi/lo A tiles + g_x;
//                   blocks 512..1023 convert hw2 -> fp16 B tiles.
// ---------------------------------------------------------------------------
__global__ __launch_bounds__(256) void k_build_prep(
    const float* __restrict__ obs, const float* __restrict__ lat,
    const float* __restrict__ hw1, const float* __restrict__ hb1,
    const float* __restrict__ hw2) {
    int tid = threadIdx.x;
    if (blockIdx.x >= 512) {
        // ---- prep B ----
        int idx = (blockIdx.x - 512) * 256 + tid;   // 131072
        int n = idx & 127, kc = (idx >> 7) & 15, d = idx >> 11;
        int k0 = kc * 8;
        uint32_t hv[4];
#pragma unroll
        for (int j = 0; j < 4; j++) {
            float v0 = hw2[(k0 + 2 * j) * 8192 + d * 128 + n];
            float v1 = hw2[(k0 + 2 * j + 1) * 8192 + d * 128 + n];
            hv[j] = (uint32_t)__half_as_ushort(__float2half_rn(v0)) |
                    ((uint32_t)__half_as_ushort(__float2half_rn(v1)) << 16);
        }
        uint8_t* base = (uint8_t*)g_bbf + d * 34816 + n * 272;
        *(uint4*)(base + k0 * 2) = make_uint4(hv[0], hv[1], hv[2], hv[3]);
        return;
    }
    // ---- build h1 ----
    __shared__ __align__(16) float sw[DIN][HID];
    __shared__ float sb[HID];
    __shared__ float sx[16][DIN];
    int n0 = blockIdx.x * 16;

    for (int i = tid; i < DIN * HID; i += 256) ((float*)sw)[i] = hw1[i];
    if (tid < HID) sb[tid] = hb1[tid];
    for (int i = tid; i < 16 * DIN; i += 256) {
        int r = i >> 6, d = i & 63;
        int n = n0 + r;
        float v = (d < 32) ? obs[(n & 511) * 32 + d] : lat[n * 32 + (d - 32)];
        sx[r][d] = v;
        g_x[n * DIN + d] = v;
    }
    __syncthreads();

    int r = tid >> 4, cg = tid & 15;
    float acc[8];
#pragma unroll
    for (int c = 0; c < 8; c++) acc[c] = 0.f;
#pragma unroll 8
    for (int d = 0; d < DIN; d++) {
        float a = sx[r][d];
        float4 w0 = *(const float4*)&sw[d][cg * 8];
        float4 w1 = *(const float4*)&sw[d][cg * 8 + 4];
        acc[0] += a * w0.x; acc[1] += a * w0.y;
        acc[2] += a * w0.z; acc[3] += a * w0.w;
        acc[4] += a * w1.x; acc[5] += a * w1.y;
        acc[6] += a * w1.z; acc[7] += a * w1.w;
    }
    int n = n0 + r;
    uint32_t hi[4], lo[4];
#pragma unroll
    for (int j = 0; j < 4; j++) {
        float v0 = fmaxf(acc[2 * j] + sb[cg * 8 + 2 * j], 0.f);
        float v1 = fmaxf(acc[2 * j + 1] + sb[cg * 8 + 2 * j + 1], 0.f);
        uint16_t h0, l0, h1, l1;
        f2hl16(v0, h0, l0);
        f2hl16(v1, h1, l1);
        hi[j] = (uint32_t)h0 | ((uint32_t)h1 << 16);
        lo[j] = (uint32_t)l0 | ((uint32_t)l1 << 16);
    }
    uint8_t* base = (uint8_t*)g_abf + (n >> 7) * 67584 + (n & 127) * 528;
    *(uint4*)(base + cg * 16) = make_uint4(hi[0], hi[1], hi[2], hi[3]);
    *(uint4*)(base + 256 + cg * 16) = make_uint4(lo[0], lo[1], lo[2], lo[3]);
}

// ---------------------------------------------------------------------------
// Kernel 1: HMMA hypernet (fp16, 2 passes: AhiBhi + AloBhi).
// Grid 128 = 64 rowblocks x 2 d-halves; 512 threads = 16 warps (4m x 4n).
// ---------------------------------------------------------------------------
#define SA_OFF    0
#define SX_OFF    67584
#define SBIAS_OFF 84480
#define SB_OFF    85504
#define SB_TILE   34816
#define HSMEM     (85504 + 2 * 34816)   // 155136

__global__ __launch_bounds__(512, 1) void k_hyper_mma(const float* __restrict__ hb2) {
    extern __shared__ __align__(128) uint8_t smem[];
    const uint32_t sbase = smem_u32(smem);
    int tid = threadIdx.x, wid = tid >> 5, lane = tid & 31;
    int rb = blockIdx.x >> 1, dh = blockIdx.x & 1;
    int n0 = rb * 128, d0 = dh * 32;
    int wm = wid & 3, wn = wid >> 2;   // warp tile: rows wm*32.. cols wn*32..

    // Prefetch A tile + B tile 0 + bias 0
    {
        const uint4* asrc = &g_abf[rb * 4224];
        for (int j = tid; j < 4224; j += 512) cp16(sbase + SA_OFF + j * 16, asrc + j);
        const uint4* bsrc = &g_bbf[d0 * 2176];
        for (int j = tid; j < 2176; j += 512) cp16(sbase + SB_OFF + j * 16, bsrc + j);
        if (tid < 32) cp16(sbase + SBIAS_OFF + tid * 16, (const uint4*)(hb2 + d0 * 128) + tid);
        CP_COMMIT();
    }
    // Stage x
    float* SX = (float*)(smem + SX_OFF);
    for (int i = tid; i < 128 * 32; i += 512) {
        int r = i >> 5, d = i & 31;
        SX[r * 33 + d] = g_x[(n0 + r) * 64 + d0 + d];
    }

    // ldmatrix lane addressing
    const int a_r = (lane & 15);
    const int a_kadd = (lane >> 4) * 8;
    const int bm = lane >> 3;
    const int b_n = ((bm >> 1) << 3) + (lane & 7);
    const int b_kadd = (bm & 1) * 8;
    const int r_q = lane >> 2;          // 0..7
    const int c_q = (lane & 3) * 2;

    float emb[2][4][4];
#pragma unroll
    for (int mt = 0; mt < 2; mt++)
#pragma unroll
        for (int t = 0; t < 4; t++)
#pragma unroll
            for (int c = 0; c < 4; c++) emb[mt][t][c] = 0.f;

    for (int i = 0; i < 32; i++) {
        int b = i & 1;
        if (i < 31) {
            const uint4* src = &g_bbf[(d0 + i + 1) * 2176];
            uint32_t dst = sbase + SB_OFF + (1 - b) * SB_TILE;
            for (int j = tid; j < 2176; j += 512) cp16(dst + j * 16, src + j);
            if (tid < 32)
                cp16(sbase + SBIAS_OFF + (1 - b) * 512 + tid * 16,
                     (const uint4*)(hb2 + (d0 + i + 1) * 128) + tid);
            CP_COMMIT();
            CP_WAIT(1);
        } else {
            CP_WAIT(0);
        }
        __syncthreads();

        const uint32_t Ab = sbase + SA_OFF;
        const uint32_t Bb = sbase + SB_OFF + b * SB_TILE;
        float S[2][4][4];
#pragma unroll
        for (int mt = 0; mt < 2; mt++)
#pragma unroll
            for (int t = 0; t < 4; t++)
#pragma unroll
                for (int c = 0; c < 4; c++) S[mt][t][c] = 0.f;

#pragma unroll
        for (int ks = 0; ks < 8; ks++) {
            uint32_t ah[2][4], al[2][4], bh[2][4];
            int ka = ks * 16 + a_kadd;
#pragma unroll
            for (int mt = 0; mt < 2; mt++) {
                int ar = wm * 32 + mt * 16 + a_r;
                ldsm_x4(ah[mt], Ab + ar * 528 + ka * 2);
                ldsm_x4(al[mt], Ab + ar * 528 + 256 + ka * 2);
            }
            int kb = ks * 16 + b_kadd;
#pragma unroll
            for (int nt = 0; nt < 2; nt++) {
                int nr = wn * 32 + nt * 16 + b_n;
                ldsm_x4(bh[nt], Bb + nr * 272 + kb * 2);
            }
#pragma unroll
            for (int mt = 0; mt < 2; mt++)
#pragma unroll
                for (int nt = 0; nt < 2; nt++) {
                    mma16816h(S[mt][nt * 2], ah[mt], bh[nt][0], bh[nt][1]);
                    mma16816h(S[mt][nt * 2], al[mt], bh[nt][0], bh[nt][1]);
                    mma16816h(S[mt][nt * 2 + 1], ah[mt], bh[nt][2], bh[nt][3]);
                    mma16816h(S[mt][nt * 2 + 1], al[mt], bh[nt][2], bh[nt][3]);
                }
        }
        // epilogue for d = d0+i
        const float* bias = (const float*)(smem + SBIAS_OFF) + b * 128;
#pragma unroll
        for (int mt = 0; mt < 2; mt++) {
            int rbase = wm * 32 + mt * 16 + r_q;
            float xlo = SX[rbase * 33 + i];
            float xhi = SX[(rbase + 8) * 33 + i];
#pragma unroll
            for (int t = 0; t < 4; t++) {
                int col = wn * 32 + t * 8 + c_q;
                float2 bv = *(const float2*)&bias[col];
                float* e = emb[mt][t];
                e[0] += xlo * fmaxf(S[mt][t][0] + bv.x, 0.f);
                e[1] += xlo * fmaxf(S[mt][t][1] + bv.y, 0.f);
                e[2] += xhi * fmaxf(S[mt][t][2] + bv.x, 0.f);
                e[3] += xhi * fmaxf(S[mt][t][3] + bv.y, 0.f);
            }
        }
        __syncthreads();
    }

    float* dst = g_embp + dh * (NTOT * HID) + n0 * 128;
#pragma unroll
    for (int mt = 0; mt < 2; mt++) {
        int row = wm * 32 + mt * 16 + r_q;
#pragma unroll
        for (int t = 0; t < 4; t++) {
            int col = wn * 32 + t * 8 + c_q;
            *(float2*)&dst[row * 128 + col] = make_float2(emb[mt][t][0], emb[mt][t][1]);
            *(float2*)&dst[(row + 8) * 128 + col] = make_float2(emb[mt][t][2], emb[mt][t][3]);
        }
    }
}

// ---------------------------------------------------------------------------
// Kernel 2: combine partials (tanh) + per-batch mean. One CTA per batch.
// ---------------------------------------------------------------------------
__global__ __launch_bounds__(256) void k_combine_mean() {
    __shared__ float red[2][128];
    int b = blockIdx.x, tid = threadIdx.x;
    int col = tid & 127, half = tid >> 7;
    float s = 0.f;
#pragma unroll
    for (int j = 0; j < 8; j++) {
        int n = b * 16 + half * 8 + j;
        float v = tanhf(g_embp[n * 128 + col] + g_embp[NTOT * HID + n * 128 + col]);
        g_emb[n * 128 + col] = v;
        s += v;
    }
    red[half][col] = s;
    __syncthreads();
    if (half == 0) g_mean[b * 128 + col] = (red[0][col] + red[1][col]) * (1.f / 16.f);
}

// ---------------------------------------------------------------------------
// Tail GEMM helper: 32 rows x 128 cols, 256 threads, 2x8 per thread.
// ---------------------------------------------------------------------------
__device__ __forceinline__ void gemm32(const float* __restrict__ sA,
                                       const float* __restrict__ sW,
                                       int tid, float acc[2][8]) {
    int tr = tid >> 4, tc = tid & 15;
    const float* ap = sA + tr * 2;
    const float* wp = sW + tc * 8;
#pragma unroll 4
    for (int k = 0; k < 128; k++) {
        float a0 = ap[k * 33], a1 = ap[k * 33 + 1];
        float4 w0 = *(const float4*)(wp + k * 128);
        float4 w1 = *(const float4*)(wp + k * 128 + 4);
        acc[0][0] += a0 * w0.x; acc[0][1] += a0 * w0.y;
        acc[0][2] += a0 * w0.z; acc[0][3] += a0 * w0.w;
        acc[0][4] += a0 * w1.x; acc[0][5] += a0 * w1.y;
        acc[0][6] += a0 * w1.z; acc[0][7] += a0 * w1.w;
        acc[1][0] += a1 * w0.x; acc[1][1] += a1 * w0.y;
        acc[1][2] += a1 * w0.z; acc[1][3] += a1 * w0.w;
        acc[1][4] += a1 * w1.x; acc[1][5] += a1 * w1.y;
        acc[1][6] += a1 * w1.z; acc[1][7] += a1 * w1.w;
    }
}

// smem floats: sA 4224 | sH 4224 | sW 16384 | sb 128 | sw3 128
#define TA 0
#define TH 4224
#define TW 8448
#define TBIAS 24832
#define TW3 24960
#define TSMEM ((24960 + 128) * 4)

__device__ void tail_val2(float* sm, int tid, int n0,
                          const float* __restrict__ W1, const float* __restrict__ b1,
                          const float* __restrict__ W2, const float* __restrict__ b2) {
    float* sA = sm + TA;
    float* sH = sm + TH;
    float* sW = sm + TW;
    float* sb = sm + TBIAS;
    int tr = tid >> 4, tc = tid & 15;

    for (int i = tid; i < 4096; i += 256) cp16(smem_u32(sW) + i * 16, (const uint4*)W1 + i);
    if (tid < 32) cp16(smem_u32(sb) + tid * 16, (const uint4*)b1 + tid);
    CP_COMMIT();
    for (int i = tid; i < 4096; i += 256) {
        int r = i >> 7, k = i & 127;
        sA[k * 33 + r] = g_emb[(n0 + r) * 128 + k];
    }
    CP_WAIT(0);
    __syncthreads();

    float acc[2][8];
#pragma unroll
    for (int r = 0; r < 2; r++)
#pragma unroll
        for (int c = 0; c < 8; c++) acc[r][c] = 0.f;
    gemm32(sA, sW, tid, acc);
#pragma unroll
    for (int r = 0; r < 2; r++)
#pragma unroll
        for (int c = 0; c < 8; c++)
            sH[(tc * 8 + c) * 33 + tr * 2 + r] = fmaxf(acc[r][c] + sb[tc * 8 + c], 0.f);
    __syncthreads();

    for (int i = tid; i < 4096; i += 256) cp16(smem_u32(sW) + i * 16, (const uint4*)W2 + i);
    if (tid < 32) cp16(smem_u32(sb) + tid * 16, (const uint4*)b2 + tid);
    CP_COMMIT();
    CP_WAIT(0);
    __syncthreads();

#pragma unroll
    for (int r = 0; r < 2; r++)
#pragma unroll
        for (int c = 0; c < 8; c++) acc[r][c] = 0.f;
    gemm32(sH, sW, tid, acc);
#pragma unroll
    for (int r = 0; r < 2; r++) {
        int n = n0 + tr * 2 + r;
#pragma unroll
        for (int c = 0; c < 8; c++)
            g_vals[n * 128 + tc * 8 + c] = fmaxf(acc[r][c] + sb[tc * 8 + c], 0.f);
    }
}

__device__ void tail_att(float* sm, int tid, int n0,
                         const float* __restrict__ W1, const float* __restrict__ b1,
                         const float* __restrict__ W2, const float* __restrict__ b2,
                         const float* __restrict__ w3, const float* __restrict__ b3) {
    float* sA = sm + TA;
    float* sH = sm + TH;
    float* sW = sm + TW;
    float* sb = sm + TBIAS;
    float* sw3 = sm + TW3;
    int tr = tid >> 4, tc = tid & 15;

    for (int i = tid; i < 4096; i += 256) cp16(smem_u32(sW) + i * 16, (const uint4*)W1 + i);
    if (tid < 32) cp16(smem_u32(sb) + tid * 16, (const uint4*)b1 + tid);
    CP_COMMIT();
    for (int i = tid; i < 4096; i += 256) {
        int r = i >> 7, k = i & 127;
        sA[k * 33 + r] = g_emb[(n0 + r) * 128 + k];
    }
    CP_WAIT(0);
    __syncthreads();

    float acc[2][8];
#pragma unroll
    for (int r = 0; r < 2; r++)
#pragma unroll
        for (int c = 0; c < 8; c++) acc[r][c] = 0.f;
    gemm32(sA, sW, tid, acc);
    __syncthreads();

    for (int i = tid; i < 4096; i += 256) cp16(smem_u32(sW) + i * 16, (const uint4*)W1 + 4096 + i);
    CP_COMMIT();
    for (int i = tid; i < 4096; i += 256) {
        int r = i >> 7, k = i & 127;
        sA[k * 33 + r] = g_mean[((n0 + r) & 511) * 128 + k];
    }
    CP_WAIT(0);
    __syncthreads();
    gemm32(sA, sW, tid, acc);
#pragma unroll
    for (int r = 0; r < 2; r++)
#pragma unroll
        for (int c = 0; c < 8; c++)
            sH[(tc * 8 + c) * 33 + tr * 2 + r] = fmaxf(acc[r][c] + sb[tc * 8 + c], 0.f);
    __syncthreads();

    for (int i = tid; i < 4096; i += 256) cp16(smem_u32(sW) + i * 16, (const uint4*)W2 + i);
    if (tid < 32) cp16(smem_u32(sb) + tid * 16, (const uint4*)b2 + tid);
    if (tid >= 32 && tid < 64) cp16(smem_u32(sw3) + (tid - 32) * 16, (const uint4*)w3 + (tid - 32));
    CP_COMMIT();
    CP_WAIT(0);
    __syncthreads();

#pragma unroll
    for (int r = 0; r < 2; r++)
#pragma unroll
        for (int c = 0; c < 8; c++) acc[r][c] = 0.f;
    gemm32(sH, sW, tid, acc);
#pragma unroll
    for (int r = 0; r < 2; r++)
#pragma unroll
        for (int c = 0; c < 8; c++)
            sA[(tc * 8 + c) * 33 + tr * 2 + r] = fmaxf(acc[r][c] + sb[tc * 8 + c], 0.f);
    __syncthreads();

    int row = tid >> 3, l8 = tid & 7;
    float s = 0.f;
#pragma unroll
    for (int k = l8; k < 128; k += 8) s += sA[k * 33 + row] * sw3[k];
    s += __shfl_xor_sync(0xffffffffu, s, 1);
    s += __shfl_xor_sync(0xffffffffu, s, 2);
    s += __shfl_xor_sync(0xffffffffu, s, 4);
    if (l8 == 0) g_sc[n0 + row] = s + b3[0];
}

// ---------------------------------------------------------------------------
// Kernel 3: fused tail — blocks 0..255 value MLP, 256..511 attention MLP.
// ---------------------------------------------------------------------------
__global__ __launch_bounds__(256, 2) void k_tail(
    const float* __restrict__ vw1, const float* __restrict__ vb1,
    const float* __restrict__ vw2, const float* __restrict__ vb2,
    const float* __restrict__ aw1, const float* __restrict__ ab1,
    const float* __restrict__ aw2, const float* __restrict__ ab2,
    const float* __restrict__ aw3, const float* __restrict__ ab3) {
    extern __shared__ __align__(16) float sm[];
    int tid = threadIdx.x;
    if (blockIdx.x < 256)
        tail_val2(sm, tid, blockIdx.x * 32, vw1, vb1, vw2, vb2);
    else
        tail_att(sm, tid, (blockIdx.x - 256) * 32, aw1, ab1, aw2, ab2, aw3, ab3);
}

// ---------------------------------------------------------------------------
// Kernel 4: softmax over 16 + weighted sum -> out[512,128]
// ---------------------------------------------------------------------------
__global__ void k_final(float* __restrict__ out) {
    __shared__ float sc[NADV];
    int b = blockIdx.x, tid = threadIdx.x;
    if (tid < NADV) sc[tid] = g_sc[b * NADV + tid];
    __syncthreads();
    float m = sc[0];
#pragma unroll
    for (int a = 1; a < NADV; a++) m = fmaxf(m, sc[a]);
    float den = 0.f, o = 0.f;
#pragma unroll
    for (int a = 0; a < NADV; a++) {
        float e = expf(sc[a] - m);
        den += e;
        o += e * g_vals[(b * NADV + a) * HID + tid];
    }
    out[b * HID + tid] = o / den;
}

// ---------------------------------------------------------------------------
extern "C" void kernel_launch(void* const* d_in, const int* in_sizes, int n_in,
                              void* d_out, int out_size) {
    const float* obs = (const float*)d_in[0];
    const float* lat = (const float*)d_in[1];
    const float* hw1 = (const float*)d_in[2];
    const float* hb1 = (const float*)d_in[3];
    const float* hw2 = (const float*)d_in[4];
    const float* hb2 = (const float*)d_in[5];
    const float* vw1 = (const float*)d_in[6];
    const float* vb1 = (const float*)d_in[7];
    const float* vw2 = (const float*)d_in[8];
    const float* vb2 = (const float*)d_in[9];
    const float* aw1 = (const float*)d_in[10];
    const float* ab1 = (const float*)d_in[11];
    const float* aw2 = (const float*)d_in[12];
    const float* ab2 = (const float*)d_in[13];
    const float* aw3 = (const float*)d_in[14];
    const float* ab3 = (const float*)d_in[15];
    float* out = (float*)d_out;

    static int attr_set = 0;
    if (!attr_set) {
        cudaFuncSetAttribute(k_hyper_mma, cudaFuncAttributeMaxDynamicSharedMemorySize, HSMEM);
        cudaFuncSetAttribute(k_tail, cudaFuncAttributeMaxDynamicSharedMemorySize, TSMEM);
        attr_set = 1;
    }

    k_build_prep<<<1024, 256>>>(obs, lat, hw1, hb1, hw2);                 // 0
    k_hyper_mma<<<128, 512, HSMEM>>>(hb2);                                // 1
    k_combine_mean<<<BATCH, 256>>>();                                     // 2
    k_tail<<<512, 256, TSMEM>>>(vw1, vb1, vw2, vb2, aw1, ab1, aw2, ab2, aw3, ab3);  // 3
    k_final<<<BATCH, HID>>>(out);                                         // 4
}

// round 8
// speedup vs baseline: 5.7145x; 1.3975x over previous
#include <cuda_runtime.h>
#include <cuda_fp16.h>
#include <math.h>
#include <stdint.h>

// Problem constants
#define NTOT 8192   // B * A
#define BATCH 512
#define NADV 16
#define DIN 64      // DS + DO
#define HID 128

// Scratch
__device__ float g_x[NTOT * DIN];
__device__ float g_emb[NTOT * HID];
__device__ float g_embp[2 * NTOT * HID];   // partial einsum sums (pre-tanh)
__device__ float g_vals[NTOT * HID];
__device__ float g_mean[BATCH * HID];
__device__ float g_sc[NTOT];
// A tiles: fp16 hi/lo, row pitch 528B; tile = 67584B = 4224 uint4
__device__ uint4 g_abf[64 * 4224];
// B tiles: fp16 hi, row pitch 272B; tile = 34816B = 2176 uint4
__device__ uint4 g_bbf[64 * 2176];

// ---------------------------------------------------------------------------
// helpers
// ---------------------------------------------------------------------------
__device__ __forceinline__ uint32_t smem_u32(const void* p) {
    uint32_t a;
    asm("{ .reg .u64 t; cvta.to.shared.u64 t, %1; cvt.u32.u64 %0, t; }" : "=r"(a) : "l"(p));
    return a;
}
__device__ __forceinline__ void f2hl16(float v, uint16_t& h, uint16_t& l) {
    __half hh = __float2half_rn(v);
    float r = v - __half2float(hh);
    __half hl = __float2half_rn(r);
    h = __half_as_ushort(hh);
    l = __half_as_ushort(hl);
}
__device__ __forceinline__ void ldsm_x4(uint32_t* r, uint32_t addr) {
    asm volatile("ldmatrix.sync.aligned.m8n8.x4.shared.b16 {%0,%1,%2,%3}, [%4];"
                 : "=r"(r[0]), "=r"(r[1]), "=r"(r[2]), "=r"(r[3]) : "r"(addr));
}
__device__ __forceinline__ void ldsm_x4_t(uint32_t* r, uint32_t addr) {
    asm volatile("ldmatrix.sync.aligned.m8n8.x4.trans.shared.b16 {%0,%1,%2,%3}, [%4];"
                 : "=r"(r[0]), "=r"(r[1]), "=r"(r[2]), "=r"(r[3]) : "r"(addr));
}
__device__ __forceinline__ void mma16816h(float* d, const uint32_t* a, uint32_t b0, uint32_t b1) {
    asm volatile(
        "mma.sync.aligned.m16n8k16.row.col.f32.f16.f16.f32 "
        "{%0,%1,%2,%3}, {%4,%5,%6,%7}, {%8,%9}, {%0,%1,%2,%3};"
        : "+f"(d[0]), "+f"(d[1]), "+f"(d[2]), "+f"(d[3])
        : "r"(a[0]), "r"(a[1]), "r"(a[2]), "r"(a[3]), "r"(b0), "r"(b1));
}
__device__ __forceinline__ void cp16(uint32_t dst, const void* src) {
    asm volatile("cp.async.cg.shared.global [%0], [%1], 16;" :: "r"(dst), "l"(src) : "memory");
}
#define CP_COMMIT() asm volatile("cp.async.commit_group;" ::: "memory")
#define CP_WAIT(N)  asm volatile("cp.async.wait_group %0;" :: "n"(N) : "memory")

// ---------------------------------------------------------------------------
// Kernel 0 (fused): blocks 0..511 build h1 -> fp16 hi/lo A tiles + g_x;
//                   blocks 512..1023 convert hw2 -> fp16 B tiles.
// ---------------------------------------------------------------------------
__global__ __launch_bounds__(256) void k_build_prep(
    const float* __restrict__ obs, const float* __restrict__ lat,
    const float* __restrict__ hw1, const float* __restrict__ hb1,
    const float* __restrict__ hw2) {
    int tid = threadIdx.x;
    if (blockIdx.x >= 512) {
        int idx = (blockIdx.x - 512) * 256 + tid;   // 131072
        int n = idx & 127, kc = (idx >> 7) & 15, d = idx >> 11;
        int k0 = kc * 8;
        uint32_t hv[4];
#pragma unroll
        for (int j = 0; j < 4; j++) {
            float v0 = hw2[(k0 + 2 * j) * 8192 + d * 128 + n];
            float v1 = hw2[(k0 + 2 * j + 1) * 8192 + d * 128 + n];
            hv[j] = (uint32_t)__half_as_ushort(__float2half_rn(v0)) |
                    ((uint32_t)__half_as_ushort(__float2half_rn(v1)) << 16);
        }
        uint8_t* base = (uint8_t*)g_bbf + d * 34816 + n * 272;
        *(uint4*)(base + k0 * 2) = make_uint4(hv[0], hv[1], hv[2], hv[3]);
        return;
    }
    __shared__ __align__(16) float sw[DIN][HID];
    __shared__ float sb[HID];
    __shared__ float sx[16][DIN];
    int n0 = blockIdx.x * 16;

    for (int i = tid; i < DIN * HID; i += 256) ((float*)sw)[i] = hw1[i];
    if (tid < HID) sb[tid] = hb1[tid];
    for (int i = tid; i < 16 * DIN; i += 256) {
        int r = i >> 6, d = i & 63;
        int n = n0 + r;
        float v = (d < 32) ? obs[(n & 511) * 32 + d] : lat[n * 32 + (d - 32)];
        sx[r][d] = v;
        g_x[n * DIN + d] = v;
    }
    __syncthreads();

    int r = tid >> 4, cg = tid & 15;
    float acc[8];
#pragma unroll
    for (int c = 0; c < 8; c++) acc[c] = 0.f;
#pragma unroll 8
    for (int d = 0; d < DIN; d++) {
        float a = sx[r][d];
        float4 w0 = *(const float4*)&sw[d][cg * 8];
        float4 w1 = *(const float4*)&sw[d][cg * 8 + 4];
        acc[0] += a * w0.x; acc[1] += a * w0.y;
        acc[2] += a * w0.z; acc[3] += a * w0.w;
        acc[4] += a * w1.x; acc[5] += a * w1.y;
        acc[6] += a * w1.z; acc[7] += a * w1.w;
    }
    int n = n0 + r;
    uint32_t hi[4], lo[4];
#pragma unroll
    for (int j = 0; j < 4; j++) {
        float v0 = fmaxf(acc[2 * j] + sb[cg * 8 + 2 * j], 0.f);
        float v1 = fmaxf(acc[2 * j + 1] + sb[cg * 8 + 2 * j + 1], 0.f);
        uint16_t h0, l0, h1, l1;
        f2hl16(v0, h0, l0);
        f2hl16(v1, h1, l1);
        hi[j] = (uint32_t)h0 | ((uint32_t)h1 << 16);
        lo[j] = (uint32_t)l0 | ((uint32_t)l1 << 16);
    }
    uint8_t* base = (uint8_t*)g_abf + (n >> 7) * 67584 + (n & 127) * 528;
    *(uint4*)(base + cg * 16) = make_uint4(hi[0], hi[1], hi[2], hi[3]);
    *(uint4*)(base + 256 + cg * 16) = make_uint4(lo[0], lo[1], lo[2], lo[3]);
}

// ---------------------------------------------------------------------------
// Kernel 1: HMMA hypernet (A hi/lo x B hi — tanh output, 2-pass OK)
// ---------------------------------------------------------------------------
#define SA_OFF    0
#define SX_OFF    67584
#define SBIAS_OFF 84480
#define SB_OFF    85504
#define SB_TILE   34816
#define HSMEM     (85504 + 2 * 34816)

__global__ __launch_bounds__(512, 1) void k_hyper_mma(const float* __restrict__ hb2) {
    extern __shared__ __align__(128) uint8_t smem[];
    const uint32_t sbase = smem_u32(smem);
    int tid = threadIdx.x, wid = tid >> 5, lane = tid & 31;
    int rb = blockIdx.x >> 1, dh = blockIdx.x & 1;
    int n0 = rb * 128, d0 = dh * 32;
    int wm = wid & 3, wn = wid >> 2;

    {
        const uint4* asrc = &g_abf[rb * 4224];
        for (int j = tid; j < 4224; j += 512) cp16(sbase + SA_OFF + j * 16, asrc + j);
        const uint4* bsrc = &g_bbf[d0 * 2176];
        for (int j = tid; j < 2176; j += 512) cp16(sbase + SB_OFF + j * 16, bsrc + j);
        if (tid < 32) cp16(sbase + SBIAS_OFF + tid * 16, (const uint4*)(hb2 + d0 * 128) + tid);
        CP_COMMIT();
    }
    float* SX = (float*)(smem + SX_OFF);
    for (int i = tid; i < 128 * 32; i += 512) {
        int r = i >> 5, d = i & 31;
        SX[r * 33 + d] = g_x[(n0 + r) * 64 + d0 + d];
    }

    const int a_r = (lane & 15);
    const int a_kadd = (lane >> 4) * 8;
    const int bm = lane >> 3;
    const int b_n = ((bm >> 1) << 3) + (lane & 7);
    const int b_kadd = (bm & 1) * 8;
    const int r_q = lane >> 2;
    const int c_q = (lane & 3) * 2;

    float emb[2][4][4];
#pragma unroll
    for (int mt = 0; mt < 2; mt++)
#pragma unroll
        for (int t = 0; t < 4; t++)
#pragma unroll
            for (int c = 0; c < 4; c++) emb[mt][t][c] = 0.f;

    for (int i = 0; i < 32; i++) {
        int b = i & 1;
        if (i < 31) {
            const uint4* src = &g_bbf[(d0 + i + 1) * 2176];
            uint32_t dst = sbase + SB_OFF + (1 - b) * SB_TILE;
            for (int j = tid; j < 2176; j += 512) cp16(dst + j * 16, src + j);
            if (tid < 32)
                cp16(sbase + SBIAS_OFF + (1 - b) * 512 + tid * 16,
                     (const uint4*)(hb2 + (d0 + i + 1) * 128) + tid);
            CP_COMMIT();
            CP_WAIT(1);
        } else {
            CP_WAIT(0);
        }
        __syncthreads();

        const uint32_t Ab = sbase + SA_OFF;
        const uint32_t Bb = sbase + SB_OFF + b * SB_TILE;
        float S[2][4][4];
#pragma unroll
        for (int mt = 0; mt < 2; mt++)
#pragma unroll
            for (int t = 0; t < 4; t++)
#pragma unroll
                for (int c = 0; c < 4; c++) S[mt][t][c] = 0.f;

#pragma unroll
        for (int ks = 0; ks < 8; ks++) {
            uint32_t ah[2][4], al[2][4], bh[2][4];
            int ka = ks * 16 + a_kadd;
#pragma unroll
            for (int mt = 0; mt < 2; mt++) {
                int ar = wm * 32 + mt * 16 + a_r;
                ldsm_x4(ah[mt], Ab + ar * 528 + ka * 2);
                ldsm_x4(al[mt], Ab + ar * 528 + 256 + ka * 2);
            }
            int kb = ks * 16 + b_kadd;
#pragma unroll
            for (int nt = 0; nt < 2; nt++) {
                int nr = wn * 32 + nt * 16 + b_n;
                ldsm_x4(bh[nt], Bb + nr * 272 + kb * 2);
            }
#pragma unroll
            for (int mt = 0; mt < 2; mt++)
#pragma unroll
                for (int nt = 0; nt < 2; nt++) {
                    mma16816h(S[mt][nt * 2], ah[mt], bh[nt][0], bh[nt][1]);
                    mma16816h(S[mt][nt * 2], al[mt], bh[nt][0], bh[nt][1]);
                    mma16816h(S[mt][nt * 2 + 1], ah[mt], bh[nt][2], bh[nt][3]);
                    mma16816h(S[mt][nt * 2 + 1], al[mt], bh[nt][2], bh[nt][3]);
                }
        }
        const float* bias = (const float*)(smem + SBIAS_OFF) + b * 128;
#pragma unroll
        for (int mt = 0; mt < 2; mt++) {
            int rbase = wm * 32 + mt * 16 + r_q;
            float xlo = SX[rbase * 33 + i];
            float xhi = SX[(rbase + 8) * 33 + i];
#pragma unroll
            for (int t = 0; t < 4; t++) {
                int col = wn * 32 + t * 8 + c_q;
                float2 bv = *(const float2*)&bias[col];
                float* e = emb[mt][t];
                e[0] += xlo * fmaxf(S[mt][t][0] + bv.x, 0.f);
                e[1] += xlo * fmaxf(S[mt][t][1] + bv.y, 0.f);
                e[2] += xhi * fmaxf(S[mt][t][2] + bv.x, 0.f);
                e[3] += xhi * fmaxf(S[mt][t][3] + bv.y, 0.f);
            }
        }
        __syncthreads();
    }

    float* dst = g_embp + dh * (NTOT * HID) + n0 * 128;
#pragma unroll
    for (int mt = 0; mt < 2; mt++) {
        int row = wm * 32 + mt * 16 + r_q;
#pragma unroll
        for (int t = 0; t < 4; t++) {
            int col = wn * 32 + t * 8 + c_q;
            *(float2*)&dst[row * 128 + col] = make_float2(emb[mt][t][0], emb[mt][t][1]);
            *(float2*)&dst[(row + 8) * 128 + col] = make_float2(emb[mt][t][2], emb[mt][t][3]);
        }
    }
}

// ---------------------------------------------------------------------------
// Kernel 2: combine partials (tanh) + per-batch mean.
// ---------------------------------------------------------------------------
__global__ __launch_bounds__(256) void k_combine_mean() {
    __shared__ float red[2][128];
    int b = blockIdx.x, tid = threadIdx.x;
    int col = tid & 127, half = tid >> 7;
    float s = 0.f;
#pragma unroll
    for (int j = 0; j < 8; j++) {
        int n = b * 16 + half * 8 + j;
        float v = tanhf(g_embp[n * 128 + col] + g_embp[NTOT * HID + n * 128 + col]);
        g_emb[n * 128 + col] = v;
        s += v;
    }
    red[half][col] = s;
    __syncthreads();
    if (half == 0) g_mean[b * 128 + col] = (red[0][col] + red[1][col]) * (1.f / 16.f);
}

// ---------------------------------------------------------------------------
// Kernel 3: HMMA tail, 3-pass (A hi/lo, W hi/lo: AhWh + AlWh + AhWl).
// 128 CTAs x 512 thr. Blocks 0..63: value MLP; 64..127: attention MLP.
// NOTE: mean_rep row n uses g_mean[n % 512] (torch tile semantics), NOT n/16.
// ---------------------------------------------------------------------------
#define TA_OFF 0
#define TW_OFF 67584
#define TB_OFF 135168
#define T3_OFF 135680
#define TSMEM  136192

__device__ __forceinline__ void t_loadW(uint8_t* smem, int tid, const float* __restrict__ W) {
    for (int i = tid; i < 8192; i += 512) {   // float2 units
        int k = i >> 6, n2 = i & 63;
        float2 v = *(const float2*)(W + k * 128 + n2 * 2);
        uint16_t h0, l0, h1, l1;
        f2hl16(v.x, h0, l0);
        f2hl16(v.y, h1, l1);
        *(uint32_t*)(smem + TW_OFF + k * 528 + n2 * 4) = (uint32_t)h0 | ((uint32_t)h1 << 16);
        *(uint32_t*)(smem + TW_OFF + k * 528 + 256 + n2 * 4) = (uint32_t)l0 | ((uint32_t)l1 << 16);
    }
}
__device__ __forceinline__ void t_loadA(uint8_t* smem, int tid, int n0, int mean_mode) {
    for (int i = tid; i < 8192; i += 512) {   // float2 units
        int row = i >> 6, c2 = i & 63;
        // tile semantics: mean_rep[n] = g_mean[n % 512]
        const float* src = mean_mode ? &g_mean[((n0 + row) & 511) * 128 + c2 * 2]
                                     : &g_emb[(n0 + row) * 128 + c2 * 2];
        float2 v = *(const float2*)src;
        uint16_t h0, l0, h1, l1;
        f2hl16(v.x, h0, l0);
        f2hl16(v.y, h1, l1);
        *(uint32_t*)(smem + TA_OFF + row * 528 + c2 * 4) = (uint32_t)h0 | ((uint32_t)h1 << 16);
        *(uint32_t*)(smem + TA_OFF + row * 528 + 256 + c2 * 4) = (uint32_t)l0 | ((uint32_t)l1 << 16);
    }
}
__device__ __forceinline__ void t_layer(uint32_t sbase, int wm, int wn, int lane,
                                        float S[2][4][4]) {
    const int a_r = lane & 15, a_kadd = (lane >> 4) * 8;
    const int b_krow = lane & 15, b_nadd = (lane >> 4) * 8;
    const uint32_t Ab = sbase + TA_OFF, Wb = sbase + TW_OFF;
#pragma unroll
    for (int ks = 0; ks < 8; ks++) {
        uint32_t ah[2][4], al[2][4], wh[2][4], wl[2][4];
        int ka = ks * 16 + a_kadd;
#pragma unroll
        for (int mt = 0; mt < 2; mt++) {
            int ar = wm * 32 + mt * 16 + a_r;
            ldsm_x4(ah[mt], Ab + ar * 528 + ka * 2);
            ldsm_x4(al[mt], Ab + ar * 528 + 256 + ka * 2);
        }
#pragma unroll
        for (int nt = 0; nt < 2; nt++) {
            uint32_t base = Wb + (ks * 16 + b_krow) * 528 + (wn * 32 + nt * 16 + b_nadd) * 2;
            ldsm_x4_t(wh[nt], base);
            ldsm_x4_t(wl[nt], base + 256);
        }
#pragma unroll
        for (int mt = 0; mt < 2; mt++)
#pragma unroll
            for (int nt = 0; nt < 2; nt++) {
                mma16816h(S[mt][nt * 2], ah[mt], wh[nt][0], wh[nt][1]);
                mma16816h(S[mt][nt * 2], al[mt], wh[nt][0], wh[nt][1]);
                mma16816h(S[mt][nt * 2], ah[mt], wl[nt][0], wl[nt][1]);
                mma16816h(S[mt][nt * 2 + 1], ah[mt], wh[nt][2], wh[nt][3]);
                mma16816h(S[mt][nt * 2 + 1], al[mt], wh[nt][2], wh[nt][3]);
                mma16816h(S[mt][nt * 2 + 1], ah[mt], wl[nt][2], wl[nt][3]);
            }
    }
}
__device__ __forceinline__ void t_act_to_sA(uint8_t* smem, int wm, int wn, int lane,
                                            float S[2][4][4]) {
    const float* bias = (const float*)(smem + TB_OFF);
    int r_q = lane >> 2, c_q = (lane & 3) * 2;
#pragma unroll
    for (int mt = 0; mt < 2; mt++) {
        int row = wm * 32 + mt * 16 + r_q;
#pragma unroll
        for (int t = 0; t < 4; t++) {
            int col = wn * 32 + t * 8 + c_q;
            float2 bv = *(const float2*)&bias[col];
            float v0 = fmaxf(S[mt][t][0] + bv.x, 0.f);
            float v1 = fmaxf(S[mt][t][1] + bv.y, 0.f);
            float v2 = fmaxf(S[mt][t][2] + bv.x, 0.f);
            float v3 = fmaxf(S[mt][t][3] + bv.y, 0.f);
            uint16_t h0, l0, h1, l1;
            f2hl16(v0, h0, l0);
            f2hl16(v1, h1, l1);
            *(uint32_t*)(smem + TA_OFF + row * 528 + col * 2) = (uint32_t)h0 | ((uint32_t)h1 << 16);
            *(uint32_t*)(smem + TA_OFF + row * 528 + 256 + col * 2) = (uint32_t)l0 | ((uint32_t)l1 << 16);
            f2hl16(v2, h0, l0);
            f2hl16(v3, h1, l1);
            *(uint32_t*)(smem + TA_OFF + (row + 8) * 528 + col * 2) = (uint32_t)h0 | ((uint32_t)h1 << 16);
            *(uint32_t*)(smem + TA_OFF + (row + 8) * 528 + 256 + col * 2) = (uint32_t)l0 | ((uint32_t)l1 << 16);
        }
    }
}

__global__ __launch_bounds__(512, 1) void k_tail_mma(
    const float* __restrict__ vw1, const float* __restrict__ vb1,
    const float* __restrict__ vw2, const float* __restrict__ vb2,
    const float* __restrict__ aw1, const float* __restrict__ ab1,
    const float* __restrict__ aw2, const float* __restrict__ ab2,
    const float* __restrict__ aw3, const float* __restrict__ ab3) {
    extern __shared__ __align__(128) uint8_t smem[];
    const uint32_t sbase = smem_u32(smem);
    int tid = threadIdx.x, wid = tid >> 5, lane = tid & 31;
    int wm = wid & 3, wn = wid >> 2;
    int r_q = lane >> 2, c_q = (lane & 3) * 2;
    float* sbias = (float*)(smem + TB_OFF);

    float S[2][4][4];
#define ZERO_S() { _Pragma("unroll") for (int mt = 0; mt < 2; mt++) \
    _Pragma("unroll") for (int t = 0; t < 4; t++) \
    _Pragma("unroll") for (int c = 0; c < 4; c++) S[mt][t][c] = 0.f; }

    if (blockIdx.x < 64) {
        // ---------------- value MLP ----------------
        int n0 = blockIdx.x * 128;
        t_loadA(smem, tid, n0, 0);
        t_loadW(smem, tid, vw1);
        if (tid < 128) sbias[tid] = vb1[tid];
        __syncthreads();
        ZERO_S();
        t_layer(sbase, wm, wn, lane, S);
        __syncthreads();
        t_act_to_sA(smem, wm, wn, lane, S);
        t_loadW(smem, tid, vw2);
        if (tid < 128) sbias[tid] = vb2[tid];
        __syncthreads();
        ZERO_S();
        t_layer(sbase, wm, wn, lane, S);
        const float* bias = sbias;
#pragma unroll
        for (int mt = 0; mt < 2; mt++) {
            int row = wm * 32 + mt * 16 + r_q;
#pragma unroll
            for (int t = 0; t < 4; t++) {
                int col = wn * 32 + t * 8 + c_q;
                float2 bv = *(const float2*)&bias[col];
                *(float2*)&g_vals[(n0 + row) * 128 + col] =
                    make_float2(fmaxf(S[mt][t][0] + bv.x, 0.f), fmaxf(S[mt][t][1] + bv.y, 0.f));
                *(float2*)&g_vals[(n0 + row + 8) * 128 + col] =
                    make_float2(fmaxf(S[mt][t][2] + bv.x, 0.f), fmaxf(S[mt][t][3] + bv.y, 0.f));
            }
        }
    } else {
        // ---------------- attention MLP ----------------
        int n0 = (blockIdx.x - 64) * 128;
        t_loadA(smem, tid, n0, 0);
        t_loadW(smem, tid, aw1);
        if (tid < 128) sbias[tid] = ab1[tid];
        __syncthreads();
        ZERO_S();
        t_layer(sbase, wm, wn, lane, S);
        __syncthreads();
        t_loadA(smem, tid, n0, 1);
        t_loadW(smem, tid, aw1 + 128 * 128);
        __syncthreads();
        t_layer(sbase, wm, wn, lane, S);
        __syncthreads();
        t_act_to_sA(smem, wm, wn, lane, S);
        t_loadW(smem, tid, aw2);
        if (tid < 128) sbias[tid] = ab2[tid];
        if (tid >= 128 && tid < 256) ((float*)(smem + T3_OFF))[tid - 128] = aw3[tid - 128];
        __syncthreads();
        ZERO_S();
        t_layer(sbase, wm, wn, lane, S);
        __syncthreads();
        t_act_to_sA(smem, wm, wn, lane, S);
        __syncthreads();
        // score: 4 threads per row
        const float* sw3 = (const float*)(smem + T3_OFF);
        int row = tid >> 2, l4 = tid & 3;
        float s = 0.f;
#pragma unroll
        for (int j = 0; j < 32; j++) {
            int k = l4 * 32 + j;
            float hi = __half2float(*(const __half*)(smem + TA_OFF + row * 528 + k * 2));
            float lo = __half2float(*(const __half*)(smem + TA_OFF + row * 528 + 256 + k * 2));
            s += (hi + lo) * sw3[k];
        }
        s += __shfl_xor_sync(0xffffffffu, s, 1);
        s += __shfl_xor_sync(0xffffffffu, s, 2);
        if (l4 == 0) g_sc[n0 + row] = s + ab3[0];
    }
}

// ---------------------------------------------------------------------------
// Kernel 4: softmax over 16 + weighted sum -> out[512,128]
// ---------------------------------------------------------------------------
__global__ void k_final(float* __restrict__ out) {
    __shared__ float sc[NADV];
    int b = blockIdx.x, tid = threadIdx.x;
    if (tid < NADV) sc[tid] = g_sc[b * NADV + tid];
    __syncthreads();
    float m = sc[0];
#pragma unroll
    for (int a = 1; a < NADV; a++) m = fmaxf(m, sc[a]);
    float den = 0.f, o = 0.f;
#pragma unroll
    for (int a = 0; a < NADV; a++) {
        float e = expf(sc[a] - m);
        den += e;
        o += e * g_vals[(b * NADV + a) * HID + tid];
    }
    out[b * HID + tid] = o / den;
}

// ---------------------------------------------------------------------------
extern "C" void kernel_launch(void* const* d_in, const int* in_sizes, int n_in,
                              void* d_out, int out_size) {
    const float* obs = (const float*)d_in[0];
    const float* lat = (const float*)d_in[1];
    const float* hw1 = (const float*)d_in[2];
    const float* hb1 = (const float*)d_in[3];
    const float* hw2 = (const float*)d_in[4];
    const float* hb2 = (const float*)d_in[5];
    const float* vw1 = (const float*)d_in[6];
    const float* vb1 = (const float*)d_in[7];
    const float* vw2 = (const float*)d_in[8];
    const float* vb2 = (const float*)d_in[9];
    const float* aw1 = (const float*)d_in[10];
    const float* ab1 = (const float*)d_in[11];
    const float* aw2 = (const float*)d_in[12];
    const float* ab2 = (const float*)d_in[13];
    const float* aw3 = (const float*)d_in[14];
    const float* ab3 = (const float*)d_in[15];
    float* out = (float*)d_out;

    static int attr_set = 0;
    if (!attr_set) {
        cudaFuncSetAttribute(k_hyper_mma, cudaFuncAttributeMaxDynamicSharedMemorySize, HSMEM);
        cudaFuncSetAttribute(k_tail_mma, cudaFuncAttributeMaxDynamicSharedMemorySize, TSMEM);
        attr_set = 1;
    }

    k_build_prep<<<1024, 256>>>(obs, lat, hw1, hb1, hw2);                 // 0
    k_hyper_mma<<<128, 512, HSMEM>>>(hb2);                                // 1
    k_combine_mean<<<BATCH, 256>>>();                                     // 2
    k_tail_mma<<<128, 512, TSMEM>>>(vw1, vb1, vw2, vb2,
                                    aw1, ab1, aw2, ab2, aw3, ab3);        // 3
    k_final<<<BATCH, HID>>>(out);                                         // 4
}

// round 9
// speedup vs baseline: 6.4574x; 1.1300x over previous
#include <cuda_runtime.h>
#include <cuda_fp16.h>
#include <math.h>
#include <stdint.h>

// Problem constants
#define NTOT 8192   // B * A
#define BATCH 512
#define NADV 16
#define DIN 64      // DS + DO
#define HID 128

// Scratch
__device__ float g_x[NTOT * DIN];
__device__ float g_embp[2 * NTOT * HID];   // partial einsum sums (pre-tanh)
__device__ float g_vals[NTOT * HID];
__device__ float g_sc[NTOT];
// fp16 hi/lo tile images, row pitch 528B (hi cols 0..127, lo 128..255, pad 8)
// one 128-row tile = 67584B = 4224 uint4
__device__ uint4 g_abf[64 * 4224];   // h1 tiles (hyper A)
__device__ uint4 g_ebf[64 * 4224];   // emb tiles (tail A)
__device__ uint4 g_mbf[4 * 4224];    // mean tiles (batches 0..511)
__device__ uint4 g_wbf[5 * 4224];    // tail weights: vw1,vw2,aw1a,aw1b,aw2 ([k][n])
// B tiles: fp16 hi only, pitch 272B; tile = 34816B = 2176 uint4
__device__ uint4 g_bbf[64 * 2176];

// ---------------------------------------------------------------------------
// helpers
// ---------------------------------------------------------------------------
__device__ __forceinline__ uint32_t smem_u32(const void* p) {
    uint32_t a;
    asm("{ .reg .u64 t; cvta.to.shared.u64 t, %1; cvt.u32.u64 %0, t; }" : "=r"(a) : "l"(p));
    return a;
}
__device__ __forceinline__ void f2hl16(float v, uint16_t& h, uint16_t& l) {
    __half hh = __float2half_rn(v);
    float r = v - __half2float(hh);
    __half hl = __float2half_rn(r);
    h = __half_as_ushort(hh);
    l = __half_as_ushort(hl);
}
__device__ __forceinline__ void pack_hl2(float v0, float v1, uint32_t& hi, uint32_t& lo) {
    uint16_t h0, l0, h1, l1;
    f2hl16(v0, h0, l0);
    f2hl16(v1, h1, l1);
    hi = (uint32_t)h0 | ((uint32_t)h1 << 16);
    lo = (uint32_t)l0 | ((uint32_t)l1 << 16);
}
__device__ __forceinline__ void ldsm_x4(uint32_t* r, uint32_t addr) {
    asm volatile("ldmatrix.sync.aligned.m8n8.x4.shared.b16 {%0,%1,%2,%3}, [%4];"
                 : "=r"(r[0]), "=r"(r[1]), "=r"(r[2]), "=r"(r[3]) : "r"(addr));
}
__device__ __forceinline__ void ldsm_x4_t(uint32_t* r, uint32_t addr) {
    asm volatile("ldmatrix.sync.aligned.m8n8.x4.trans.shared.b16 {%0,%1,%2,%3}, [%4];"
                 : "=r"(r[0]), "=r"(r[1]), "=r"(r[2]), "=r"(r[3]) : "r"(addr));
}
__device__ __forceinline__ void mma16816h(float* d, const uint32_t* a, uint32_t b0, uint32_t b1) {
    asm volatile(
        "mma.sync.aligned.m16n8k16.row.col.f32.f16.f16.f32 "
        "{%0,%1,%2,%3}, {%4,%5,%6,%7}, {%8,%9}, {%0,%1,%2,%3};"
        : "+f"(d[0]), "+f"(d[1]), "+f"(d[2]), "+f"(d[3])
        : "r"(a[0]), "r"(a[1]), "r"(a[2]), "r"(a[3]), "r"(b0), "r"(b1));
}
__device__ __forceinline__ void cp16(uint32_t dst, const void* src) {
    asm volatile("cp.async.cg.shared.global [%0], [%1], 16;" :: "r"(dst), "l"(src) : "memory");
}
#define CP_COMMIT() asm volatile("cp.async.commit_group;" ::: "memory")
#define CP_WAIT(N)  asm volatile("cp.async.wait_group %0;" :: "n"(N) : "memory")

// ---------------------------------------------------------------------------
// Kernel 0 (fused): blocks 0..511 build h1 -> A tiles + g_x;
//   blocks 512..1023: hw2 -> B tiles; blocks 1024..1063: tail weights -> g_wbf
// ---------------------------------------------------------------------------
__global__ __launch_bounds__(256) void k_build_prep(
    const float* __restrict__ obs, const float* __restrict__ lat,
    const float* __restrict__ hw1, const float* __restrict__ hb1,
    const float* __restrict__ hw2,
    const float* __restrict__ vw1, const float* __restrict__ vw2,
    const float* __restrict__ aw1, const float* __restrict__ aw2) {
    int tid = threadIdx.x;
    if (blockIdx.x >= 1024) {
        // ---- prep tail weights: [k][n] fp16 hi/lo, pitch 528 ----
        int idx = (blockIdx.x - 1024) * 256 + tid;  // 10240
        int t = idx >> 11;                           // 0..4
        int rem = idx & 2047;
        int k = rem >> 4, c = rem & 15;
        const float* W = (t == 0) ? vw1 : (t == 1) ? vw2 : (t == 2) ? aw1
                         : (t == 3) ? (aw1 + 16384) : aw2;
        uint32_t hi[4], lo[4];
#pragma unroll
        for (int j = 0; j < 4; j++) {
            float2 v = *(const float2*)(W + k * 128 + c * 8 + 2 * j);
            pack_hl2(v.x, v.y, hi[j], lo[j]);
        }
        uint8_t* base = (uint8_t*)g_wbf + t * 67584 + k * 528;
        *(uint4*)(base + c * 16) = make_uint4(hi[0], hi[1], hi[2], hi[3]);
        *(uint4*)(base + 256 + c * 16) = make_uint4(lo[0], lo[1], lo[2], lo[3]);
        return;
    }
    if (blockIdx.x >= 512) {
        // ---- prep B (hw2 -> fp16 hi, [n][k], pitch 272) ----
        int idx = (blockIdx.x - 512) * 256 + tid;   // 131072
        int n = idx & 127, kc = (idx >> 7) & 15, d = idx >> 11;
        int k0 = kc * 8;
        uint32_t hv[4];
#pragma unroll
        for (int j = 0; j < 4; j++) {
            float v0 = hw2[(k0 + 2 * j) * 8192 + d * 128 + n];
            float v1 = hw2[(k0 + 2 * j + 1) * 8192 + d * 128 + n];
            hv[j] = (uint32_t)__half_as_ushort(__float2half_rn(v0)) |
                    ((uint32_t)__half_as_ushort(__float2half_rn(v1)) << 16);
        }
        uint8_t* base = (uint8_t*)g_bbf + d * 34816 + n * 272;
        *(uint4*)(base + k0 * 2) = make_uint4(hv[0], hv[1], hv[2], hv[3]);
        return;
    }
    // ---- build h1 ----
    __shared__ __align__(16) float sw[DIN][HID];
    __shared__ float sb[HID];
    __shared__ float sx[16][DIN];
    int n0 = blockIdx.x * 16;

    for (int i = tid; i < DIN * HID; i += 256) ((float*)sw)[i] = hw1[i];
    if (tid < HID) sb[tid] = hb1[tid];
    for (int i = tid; i < 16 * DIN; i += 256) {
        int r = i >> 6, d = i & 63;
        int n = n0 + r;
        float v = (d < 32) ? obs[(n & 511) * 32 + d] : lat[n * 32 + (d - 32)];
        sx[r][d] = v;
        g_x[n * DIN + d] = v;
    }
    __syncthreads();

    int r = tid >> 4, cg = tid & 15;
    float acc[8];
#pragma unroll
    for (int c = 0; c < 8; c++) acc[c] = 0.f;
#pragma unroll 8
    for (int d = 0; d < DIN; d++) {
        float a = sx[r][d];
        float4 w0 = *(const float4*)&sw[d][cg * 8];
        float4 w1 = *(const float4*)&sw[d][cg * 8 + 4];
        acc[0] += a * w0.x; acc[1] += a * w0.y;
        acc[2] += a * w0.z; acc[3] += a * w0.w;
        acc[4] += a * w1.x; acc[5] += a * w1.y;
        acc[6] += a * w1.z; acc[7] += a * w1.w;
    }
    int n = n0 + r;
    uint32_t hi[4], lo[4];
#pragma unroll
    for (int j = 0; j < 4; j++)
        pack_hl2(fmaxf(acc[2 * j] + sb[cg * 8 + 2 * j], 0.f),
                 fmaxf(acc[2 * j + 1] + sb[cg * 8 + 2 * j + 1], 0.f), hi[j], lo[j]);
    uint8_t* base = (uint8_t*)g_abf + (n >> 7) * 67584 + (n & 127) * 528;
    *(uint4*)(base + cg * 16) = make_uint4(hi[0], hi[1], hi[2], hi[3]);
    *(uint4*)(base + 256 + cg * 16) = make_uint4(lo[0], lo[1], lo[2], lo[3]);
}

// ---------------------------------------------------------------------------
// Kernel 1: HMMA hypernet (A hi/lo x B hi; tanh downstream, 2-pass OK)
// ---------------------------------------------------------------------------
#define SA_OFF    0
#define SX_OFF    67584
#define SBIAS_OFF 84480
#define SB_OFF    85504
#define SB_TILE   34816
#define HSMEM     (85504 + 2 * 34816)

__global__ __launch_bounds__(512, 1) void k_hyper_mma(const float* __restrict__ hb2) {
    extern __shared__ __align__(128) uint8_t smem[];
    const uint32_t sbase = smem_u32(smem);
    int tid = threadIdx.x, wid = tid >> 5, lane = tid & 31;
    int rb = blockIdx.x >> 1, dh = blockIdx.x & 1;
    int n0 = rb * 128, d0 = dh * 32;
    int wm = wid & 3, wn = wid >> 2;

    {
        const uint4* asrc = &g_abf[rb * 4224];
        for (int j = tid; j < 4224; j += 512) cp16(sbase + SA_OFF + j * 16, asrc + j);
        const uint4* bsrc = &g_bbf[d0 * 2176];
        for (int j = tid; j < 2176; j += 512) cp16(sbase + SB_OFF + j * 16, bsrc + j);
        if (tid < 32) cp16(sbase + SBIAS_OFF + tid * 16, (const uint4*)(hb2 + d0 * 128) + tid);
        CP_COMMIT();
    }
    float* SX = (float*)(smem + SX_OFF);
    for (int i = tid; i < 128 * 32; i += 512) {
        int r = i >> 5, d = i & 31;
        SX[r * 33 + d] = g_x[(n0 + r) * 64 + d0 + d];
    }

    const int a_r = (lane & 15);
    const int a_kadd = (lane >> 4) * 8;
    const int bm = lane >> 3;
    const int b_n = ((bm >> 1) << 3) + (lane & 7);
    const int b_kadd = (bm & 1) * 8;
    const int r_q = lane >> 2;
    const int c_q = (lane & 3) * 2;

    float emb[2][4][4];
#pragma unroll
    for (int mt = 0; mt < 2; mt++)
#pragma unroll
        for (int t = 0; t < 4; t++)
#pragma unroll
            for (int c = 0; c < 4; c++) emb[mt][t][c] = 0.f;

    for (int i = 0; i < 32; i++) {
        int b = i & 1;
        if (i < 31) {
            const uint4* src = &g_bbf[(d0 + i + 1) * 2176];
            uint32_t dst = sbase + SB_OFF + (1 - b) * SB_TILE;
            for (int j = tid; j < 2176; j += 512) cp16(dst + j * 16, src + j);
            if (tid < 32)
                cp16(sbase + SBIAS_OFF + (1 - b) * 512 + tid * 16,
                     (const uint4*)(hb2 + (d0 + i + 1) * 128) + tid);
            CP_COMMIT();
            CP_WAIT(1);
        } else {
            CP_WAIT(0);
        }
        __syncthreads();

        const uint32_t Ab = sbase + SA_OFF;
        const uint32_t Bb = sbase + SB_OFF + b * SB_TILE;
        float S[2][4][4];
#pragma unroll
        for (int mt = 0; mt < 2; mt++)
#pragma unroll
            for (int t = 0; t < 4; t++)
#pragma unroll
                for (int c = 0; c < 4; c++) S[mt][t][c] = 0.f;

#pragma unroll
        for (int ks = 0; ks < 8; ks++) {
            uint32_t ah[2][4], al[2][4], bh[2][4];
            int ka = ks * 16 + a_kadd;
#pragma unroll
            for (int mt = 0; mt < 2; mt++) {
                int ar = wm * 32 + mt * 16 + a_r;
                ldsm_x4(ah[mt], Ab + ar * 528 + ka * 2);
                ldsm_x4(al[mt], Ab + ar * 528 + 256 + ka * 2);
            }
            int kb = ks * 16 + b_kadd;
#pragma unroll
            for (int nt = 0; nt < 2; nt++) {
                int nr = wn * 32 + nt * 16 + b_n;
                ldsm_x4(bh[nt], Bb + nr * 272 + kb * 2);
            }
#pragma unroll
            for (int mt = 0; mt < 2; mt++)
#pragma unroll
                for (int nt = 0; nt < 2; nt++) {
                    mma16816h(S[mt][nt * 2], ah[mt], bh[nt][0], bh[nt][1]);
                    mma16816h(S[mt][nt * 2], al[mt], bh[nt][0], bh[nt][1]);
                    mma16816h(S[mt][nt * 2 + 1], ah[mt], bh[nt][2], bh[nt][3]);
                    mma16816h(S[mt][nt * 2 + 1], al[mt], bh[nt][2], bh[nt][3]);
                }
        }
        const float* bias = (const float*)(smem + SBIAS_OFF) + b * 128;
#pragma unroll
        for (int mt = 0; mt < 2; mt++) {
            int rbase = wm * 32 + mt * 16 + r_q;
            float xlo = SX[rbase * 33 + i];
            float xhi = SX[(rbase + 8) * 33 + i];
#pragma unroll
            for (int t = 0; t < 4; t++) {
                int col = wn * 32 + t * 8 + c_q;
                float2 bv = *(const float2*)&bias[col];
                float* e = emb[mt][t];
                e[0] += xlo * fmaxf(S[mt][t][0] + bv.x, 0.f);
                e[1] += xlo * fmaxf(S[mt][t][1] + bv.y, 0.f);
                e[2] += xhi * fmaxf(S[mt][t][2] + bv.x, 0.f);
                e[3] += xhi * fmaxf(S[mt][t][3] + bv.y, 0.f);
            }
        }
        __syncthreads();
    }

    float* dst = g_embp + dh * (NTOT * HID) + n0 * 128;
#pragma unroll
    for (int mt = 0; mt < 2; mt++) {
        int row = wm * 32 + mt * 16 + r_q;
#pragma unroll
        for (int t = 0; t < 4; t++) {
            int col = wn * 32 + t * 8 + c_q;
            *(float2*)&dst[row * 128 + col] = make_float2(emb[mt][t][0], emb[mt][t][1]);
            *(float2*)&dst[(row + 8) * 128 + col] = make_float2(emb[mt][t][2], emb[mt][t][3]);
        }
    }
}

// ---------------------------------------------------------------------------
// Kernel 2: combine partials (tanh) -> fp16 hi/lo emb tiles + mean tiles.
// One CTA per batch (512 CTAs, 256 threads).
// ---------------------------------------------------------------------------
__global__ __launch_bounds__(256) void k_combine_mean() {
    __shared__ float2 red[4][64];
    int b = blockIdx.x, tid = threadIdx.x;
    int c2 = tid & 63, rg = tid >> 6;  // float2 col, row-group
    uint8_t* ebase = (uint8_t*)g_ebf + (b >> 3) * 67584 + ((b & 7) * 16) * 528;
    float2 sum = make_float2(0.f, 0.f);
#pragma unroll
    for (int r = 0; r < 4; r++) {
        int row = rg * 4 + r;
        int n = b * 16 + row;
        float2 p0 = *(const float2*)&g_embp[n * 128 + 2 * c2];
        float2 p1 = *(const float2*)&g_embp[NTOT * HID + n * 128 + 2 * c2];
        float v0 = tanhf(p0.x + p1.x), v1 = tanhf(p0.y + p1.y);
        sum.x += v0;
        sum.y += v1;
        uint32_t hi, lo;
        pack_hl2(v0, v1, hi, lo);
        *(uint32_t*)(ebase + row * 528 + c2 * 4) = hi;
        *(uint32_t*)(ebase + row * 528 + 256 + c2 * 4) = lo;
    }
    red[rg][c2] = sum;
    __syncthreads();
    if (rg == 0) {
        float2 m;
        m.x = (red[0][c2].x + red[1][c2].x + red[2][c2].x + red[3][c2].x) * (1.f / 16.f);
        m.y = (red[0][c2].y + red[1][c2].y + red[2][c2].y + red[3][c2].y) * (1.f / 16.f);
        uint32_t hi, lo;
        pack_hl2(m.x, m.y, hi, lo);
        uint8_t* mbase = (uint8_t*)g_mbf + (b >> 7) * 67584 + (b & 127) * 528;
        *(uint32_t*)(mbase + c2 * 4) = hi;
        *(uint32_t*)(mbase + 256 + c2 * 4) = lo;
    }
}

// ---------------------------------------------------------------------------
// Kernel 3: pipelined HMMA tail. 128 CTAs x 512 thr.
// Blocks 0..63: value MLP; 64..127: attention MLP. All operands pre-converted;
// cp.async double-buffered weights. 3-pass per layer (AhWh+AlWh+AhWl).
// smem: sA 67584 | sW0 67584 | sW1 67584 | bias 1024 | w3 512 = 204288
// ---------------------------------------------------------------------------
#define TA_OFF  0
#define TW0_OFF 67584
#define TW1_OFF 135168
#define TB_OFF  202752
#define T3_OFF  203776
#define TSMEM   204288

__device__ __forceinline__ void t_layer(uint32_t sbase, uint32_t Wb, int wm, int wn, int lane,
                                        float S[2][4][4]) {
    const int a_r = lane & 15, a_kadd = (lane >> 4) * 8;
    const int b_krow = lane & 15, b_nadd = (lane >> 4) * 8;
    const uint32_t Ab = sbase + TA_OFF;
#pragma unroll
    for (int ks = 0; ks < 8; ks++) {
        uint32_t ah[2][4], al[2][4], wh[2][4], wl[2][4];
        int ka = ks * 16 + a_kadd;
#pragma unroll
        for (int mt = 0; mt < 2; mt++) {
            int ar = wm * 32 + mt * 16 + a_r;
            ldsm_x4(ah[mt], Ab + ar * 528 + ka * 2);
            ldsm_x4(al[mt], Ab + ar * 528 + 256 + ka * 2);
        }
#pragma unroll
        for (int nt = 0; nt < 2; nt++) {
            uint32_t base = Wb + (ks * 16 + b_krow) * 528 + (wn * 32 + nt * 16 + b_nadd) * 2;
            ldsm_x4_t(wh[nt], base);
            ldsm_x4_t(wl[nt], base + 256);
        }
#pragma unroll
        for (int mt = 0; mt < 2; mt++)
#pragma unroll
            for (int nt = 0; nt < 2; nt++) {
                mma16816h(S[mt][nt * 2], ah[mt], wh[nt][0], wh[nt][1]);
                mma16816h(S[mt][nt * 2], al[mt], wh[nt][0], wh[nt][1]);
                mma16816h(S[mt][nt * 2], ah[mt], wl[nt][0], wl[nt][1]);
                mma16816h(S[mt][nt * 2 + 1], ah[mt], wh[nt][2], wh[nt][3]);
                mma16816h(S[mt][nt * 2 + 1], al[mt], wh[nt][2], wh[nt][3]);
                mma16816h(S[mt][nt * 2 + 1], ah[mt], wl[nt][2], wl[nt][3]);
            }
    }
}
__device__ __forceinline__ void t_act_to_sA(uint8_t* smem, const float* bias,
                                            int wm, int wn, int lane, float S[2][4][4]) {
    int r_q = lane >> 2, c_q = (lane & 3) * 2;
#pragma unroll
    for (int mt = 0; mt < 2; mt++) {
        int row = wm * 32 + mt * 16 + r_q;
#pragma unroll
        for (int t = 0; t < 4; t++) {
            int col = wn * 32 + t * 8 + c_q;
            float2 bv = *(const float2*)&bias[col];
            uint32_t hi, lo;
            pack_hl2(fmaxf(S[mt][t][0] + bv.x, 0.f), fmaxf(S[mt][t][1] + bv.y, 0.f), hi, lo);
            *(uint32_t*)(smem + TA_OFF + row * 528 + col * 2) = hi;
            *(uint32_t*)(smem + TA_OFF + row * 528 + 256 + col * 2) = lo;
            pack_hl2(fmaxf(S[mt][t][2] + bv.x, 0.f), fmaxf(S[mt][t][3] + bv.y, 0.f), hi, lo);
            *(uint32_t*)(smem + TA_OFF + (row + 8) * 528 + col * 2) = hi;
            *(uint32_t*)(smem + TA_OFF + (row + 8) * 528 + 256 + col * 2) = lo;
        }
    }
}

__global__ __launch_bounds__(512, 1) void k_tail_mma(
    const float* __restrict__ vb1, const float* __restrict__ vb2,
    const float* __restrict__ ab1, const float* __restrict__ ab2,
    const float* __restrict__ aw3, const float* __restrict__ ab3) {
    extern __shared__ __align__(128) uint8_t smem[];
    const uint32_t sbase = smem_u32(smem);
    int tid = threadIdx.x, wid = tid >> 5, lane = tid & 31;
    int wm = wid & 3, wn = wid >> 2;
    int r_q = lane >> 2, c_q = (lane & 3) * 2;
    float* b0 = (float*)(smem + TB_OFF);
    float* b1 = b0 + 128;

    float S[2][4][4];
#define ZERO_S() { _Pragma("unroll") for (int mt = 0; mt < 2; mt++) \
    _Pragma("unroll") for (int t = 0; t < 4; t++) \
    _Pragma("unroll") for (int c = 0; c < 4; c++) S[mt][t][c] = 0.f; }

    if (blockIdx.x < 64) {
        // ---------------- value MLP ----------------
        int n0 = blockIdx.x * 128;
        // group0: A (emb tile) + W0 (vw1)
        for (int j = tid; j < 4224; j += 512) cp16(sbase + TA_OFF + j * 16, &g_ebf[blockIdx.x * 4224 + j]);
        for (int j = tid; j < 4224; j += 512) cp16(sbase + TW0_OFF + j * 16, &g_wbf[0 * 4224 + j]);
        CP_COMMIT();
        // group1: W1 (vw2)
        for (int j = tid; j < 4224; j += 512) cp16(sbase + TW1_OFF + j * 16, &g_wbf[1 * 4224 + j]);
        CP_COMMIT();
        if (tid < 128) b0[tid] = vb1[tid];
        else if (tid < 256) b1[tid - 128] = vb2[tid - 128];
        CP_WAIT(1);
        __syncthreads();
        ZERO_S();
        t_layer(sbase, sbase + TW0_OFF, wm, wn, lane, S);
        __syncthreads();
        t_act_to_sA(smem, b0, wm, wn, lane, S);
        CP_WAIT(0);
        __syncthreads();
        ZERO_S();
        t_layer(sbase, sbase + TW1_OFF, wm, wn, lane, S);
#pragma unroll
        for (int mt = 0; mt < 2; mt++) {
            int row = wm * 32 + mt * 16 + r_q;
#pragma unroll
            for (int t = 0; t < 4; t++) {
                int col = wn * 32 + t * 8 + c_q;
                float2 bv = *(const float2*)&b1[col];
                *(float2*)&g_vals[(n0 + row) * 128 + col] =
                    make_float2(fmaxf(S[mt][t][0] + bv.x, 0.f), fmaxf(S[mt][t][1] + bv.y, 0.f));
                *(float2*)&g_vals[(n0 + row + 8) * 128 + col] =
                    make_float2(fmaxf(S[mt][t][2] + bv.x, 0.f), fmaxf(S[mt][t][3] + bv.y, 0.f));
            }
        }
    } else {
        // ---------------- attention MLP ----------------
        int cb = blockIdx.x - 64;
        int n0 = cb * 128;
        // group0: A (emb tile) + W0 (aw1a)
        for (int j = tid; j < 4224; j += 512) cp16(sbase + TA_OFF + j * 16, &g_ebf[cb * 4224 + j]);
        for (int j = tid; j < 4224; j += 512) cp16(sbase + TW0_OFF + j * 16, &g_wbf[2 * 4224 + j]);
        CP_COMMIT();
        // group1: W1 (aw1b)
        for (int j = tid; j < 4224; j += 512) cp16(sbase + TW1_OFF + j * 16, &g_wbf[3 * 4224 + j]);
        CP_COMMIT();
        if (tid < 128) b0[tid] = ab1[tid];
        else if (tid < 256) b1[tid - 128] = ab2[tid - 128];
        else if (tid < 384) ((float*)(smem + T3_OFF))[tid - 256] = aw3[tid - 256];
        CP_WAIT(1);
        __syncthreads();
        ZERO_S();
        t_layer(sbase, sbase + TW0_OFF, wm, wn, lane, S);  // layer1a (emb x aw1a)
        __syncthreads();
        // group2: mean tile -> sA ; group3: aw2 -> sW0
        for (int j = tid; j < 4224; j += 512) cp16(sbase + TA_OFF + j * 16, &g_mbf[(cb & 3) * 4224 + j]);
        CP_COMMIT();
        for (int j = tid; j < 4224; j += 512) cp16(sbase + TW0_OFF + j * 16, &g_wbf[4 * 4224 + j]);
        CP_COMMIT();
        CP_WAIT(1);   // mean arrived
        __syncthreads();
        t_layer(sbase, sbase + TW1_OFF, wm, wn, lane, S);  // layer1b (mean x aw1b), accumulate
        __syncthreads();
        t_act_to_sA(smem, b0, wm, wn, lane, S);
        CP_WAIT(0);   // aw2 arrived
        __syncthreads();
        ZERO_S();
        t_layer(sbase, sbase + TW0_OFF, wm, wn, lane, S);  // layer2
        __syncthreads();
        t_act_to_sA(smem, b1, wm, wn, lane, S);
        __syncthreads();
        // score: 4 threads per row
        const float* sw3 = (const float*)(smem + T3_OFF);
        int row = tid >> 2, l4 = tid & 3;
        float s = 0.f;
#pragma unroll
        for (int j = 0; j < 32; j++) {
            int k = l4 * 32 + j;
            float hi = __half2float(*(const __half*)(smem + TA_OFF + row * 528 + k * 2));
            float lo = __half2float(*(const __half*)(smem + TA_OFF + row * 528 + 256 + k * 2));
            s += (hi + lo) * sw3[k];
        }
        s += __shfl_xor_sync(0xffffffffu, s, 1);
        s += __shfl_xor_sync(0xffffffffu, s, 2);
        if (l4 == 0) g_sc[n0 + row] = s + ab3[0];
    }
}

// ---------------------------------------------------------------------------
// Kernel 4: softmax over 16 + weighted sum -> out[512,128]
// ---------------------------------------------------------------------------
__global__ void k_final(float* __restrict__ out) {
    __shared__ float sc[NADV];
    int b = blockIdx.x, tid = threadIdx.x;
    if (tid < NADV) sc[tid] = g_sc[b * NADV + tid];
    __syncthreads();
    float m = sc[0];
#pragma unroll
    for (int a = 1; a < NADV; a++) m = fmaxf(m, sc[a]);
    float den = 0.f, o = 0.f;
#pragma unroll
    for (int a = 0; a < NADV; a++) {
        float e = expf(sc[a] - m);
        den += e;
        o += e * g_vals[(b * NADV + a) * HID + tid];
    }
    out[b * HID + tid] = o / den;
}

// ---------------------------------------------------------------------------
extern "C" void kernel_launch(void* const* d_in, const int* in_sizes, int n_in,
                              void* d_out, int out_size) {
    const float* obs = (const float*)d_in[0];
    const float* lat = (const float*)d_in[1];
    const float* hw1 = (const float*)d_in[2];
    const float* hb1 = (const float*)d_in[3];
    const float* hw2 = (const float*)d_in[4];
    const float* hb2 = (const float*)d_in[5];
    const float* vw1 = (const float*)d_in[6];
    const float* vb1 = (const float*)d_in[7];
    const float* vw2 = (const float*)d_in[8];
    const float* vb2 = (const float*)d_in[9];
    const float* aw1 = (const float*)d_in[10];
    const float* ab1 = (const float*)d_in[11];
    const float* aw2 = (const float*)d_in[12];
    const float* ab2 = (const float*)d_in[13];
    const float* aw3 = (const float*)d_in[14];
    const float* ab3 = (const float*)d_in[15];
    float* out = (float*)d_out;

    static int attr_set = 0;
    if (!attr_set) {
        cudaFuncSetAttribute(k_hyper_mma, cudaFuncAttributeMaxDynamicSharedMemorySize, HSMEM);
        cudaFuncSetAttribute(k_tail_mma, cudaFuncAttributeMaxDynamicSharedMemorySize, TSMEM);
        attr_set = 1;
    }

    k_build_prep<<<1064, 256>>>(obs, lat, hw1, hb1, hw2, vw1, vw2, aw1, aw2);  // 0
    k_hyper_mma<<<128, 512, HSMEM>>>(hb2);                                     // 1
    k_combine_mean<<<BATCH, 256>>>();                                          // 2
    k_tail_mma<<<128, 512, TSMEM>>>(vb1, vb2, ab1, ab2, aw3, ab3);             // 3
    k_final<<<BATCH, HID>>>(out);                                              // 4
}

// round 10
// speedup vs baseline: 6.6959x; 1.0369x over previous
#include <cuda_runtime.h>
#include <cuda_fp16.h>
#include <math.h>
#include <stdint.h>

// Problem constants
#define NTOT 8192   // B * A
#define BATCH 512
#define NADV 16
#define DIN 64      // DS + DO
#define HID 128

// Scratch
__device__ float g_x[NTOT * DIN];
__device__ float g_embp[2 * NTOT * HID];   // partial einsum sums (pre-tanh)
__device__ float g_vals[NTOT * HID];
__device__ float g_sc[NTOT];
// fp16 hi/lo tile images, row pitch 528B (hi cols 0..127, lo 128..255, pad 8)
// one 128-row tile = 67584B = 4224 uint4
__device__ uint4 g_abf[64 * 4224];   // h1 tiles (hyper A)
__device__ uint4 g_ebf[64 * 4224];   // emb tiles (tail A)
__device__ uint4 g_mbf[4 * 4224];    // mean tiles (batches 0..511)
__device__ uint4 g_wbf[5 * 4224];    // tail weights: vw1,vw2,aw1a,aw1b,aw2 ([k][n])
// B tiles: fp16 hi only, pitch 272B; tile = 34816B = 2176 uint4
__device__ uint4 g_bbf[64 * 2176];

// ---------------------------------------------------------------------------
// helpers
// ---------------------------------------------------------------------------
__device__ __forceinline__ uint32_t smem_u32(const void* p) {
    uint32_t a;
    asm("{ .reg .u64 t; cvta.to.shared.u64 t, %1; cvt.u32.u64 %0, t; }" : "=r"(a) : "l"(p));
    return a;
}
__device__ __forceinline__ void f2hl16(float v, uint16_t& h, uint16_t& l) {
    __half hh = __float2half_rn(v);
    float r = v - __half2float(hh);
    __half hl = __float2half_rn(r);
    h = __half_as_ushort(hh);
    l = __half_as_ushort(hl);
}
__device__ __forceinline__ void pack_hl2(float v0, float v1, uint32_t& hi, uint32_t& lo) {
    uint16_t h0, l0, h1, l1;
    f2hl16(v0, h0, l0);
    f2hl16(v1, h1, l1);
    hi = (uint32_t)h0 | ((uint32_t)h1 << 16);
    lo = (uint32_t)l0 | ((uint32_t)l1 << 16);
}
__device__ __forceinline__ void ldsm_x4(uint32_t* r, uint32_t addr) {
    asm volatile("ldmatrix.sync.aligned.m8n8.x4.shared.b16 {%0,%1,%2,%3}, [%4];"
                 : "=r"(r[0]), "=r"(r[1]), "=r"(r[2]), "=r"(r[3]) : "r"(addr));
}
__device__ __forceinline__ void ldsm_x4_t(uint32_t* r, uint32_t addr) {
    asm volatile("ldmatrix.sync.aligned.m8n8.x4.trans.shared.b16 {%0,%1,%2,%3}, [%4];"
                 : "=r"(r[0]), "=r"(r[1]), "=r"(r[2]), "=r"(r[3]) : "r"(addr));
}
__device__ __forceinline__ void mma16816h(float* d, const uint32_t* a, uint32_t b0, uint32_t b1) {
    asm volatile(
        "mma.sync.aligned.m16n8k16.row.col.f32.f16.f16.f32 "
        "{%0,%1,%2,%3}, {%4,%5,%6,%7}, {%8,%9}, {%0,%1,%2,%3};"
        : "+f"(d[0]), "+f"(d[1]), "+f"(d[2]), "+f"(d[3])
        : "r"(a[0]), "r"(a[1]), "r"(a[2]), "r"(a[3]), "r"(b0), "r"(b1));
}
__device__ __forceinline__ void cp16(uint32_t dst, const void* src) {
    asm volatile("cp.async.cg.shared.global [%0], [%1], 16;" :: "r"(dst), "l"(src) : "memory");
}
#define CP_COMMIT() asm volatile("cp.async.commit_group;" ::: "memory")
#define CP_WAIT(N)  asm volatile("cp.async.wait_group %0;" :: "n"(N) : "memory")

// ---------------------------------------------------------------------------
// Kernel 0: build h1 -> fp16 hi/lo A tiles + g_x
// ---------------------------------------------------------------------------
__global__ __launch_bounds__(256) void k_h1(
    const float* __restrict__ obs, const float* __restrict__ lat,
    const float* __restrict__ hw1, const float* __restrict__ hb1) {
    __shared__ __align__(16) float sw[DIN][HID];
    __shared__ float sb[HID];
    __shared__ float sx[16][DIN];
    int tid = threadIdx.x;
    int n0 = blockIdx.x * 16;

    for (int i = tid; i < DIN * HID; i += 256) ((float*)sw)[i] = hw1[i];
    if (tid < HID) sb[tid] = hb1[tid];
    for (int i = tid; i < 16 * DIN; i += 256) {
        int r = i >> 6, d = i & 63;
        int n = n0 + r;
        float v = (d < 32) ? obs[(n & 511) * 32 + d] : lat[n * 32 + (d - 32)];
        sx[r][d] = v;
        g_x[n * DIN + d] = v;
    }
    __syncthreads();

    int r = tid >> 4, cg = tid & 15;
    float acc[8];
#pragma unroll
    for (int c = 0; c < 8; c++) acc[c] = 0.f;
#pragma unroll 8
    for (int d = 0; d < DIN; d++) {
        float a = sx[r][d];
        float4 w0 = *(const float4*)&sw[d][cg * 8];
        float4 w1 = *(const float4*)&sw[d][cg * 8 + 4];
        acc[0] += a * w0.x; acc[1] += a * w0.y;
        acc[2] += a * w0.z; acc[3] += a * w0.w;
        acc[4] += a * w1.x; acc[5] += a * w1.y;
        acc[6] += a * w1.z; acc[7] += a * w1.w;
    }
    int n = n0 + r;
    uint32_t hi[4], lo[4];
#pragma unroll
    for (int j = 0; j < 4; j++)
        pack_hl2(fmaxf(acc[2 * j] + sb[cg * 8 + 2 * j], 0.f),
                 fmaxf(acc[2 * j + 1] + sb[cg * 8 + 2 * j + 1], 0.f), hi[j], lo[j]);
    uint8_t* base = (uint8_t*)g_abf + (n >> 7) * 67584 + (n & 127) * 528;
    *(uint4*)(base + cg * 16) = make_uint4(hi[0], hi[1], hi[2], hi[3]);
    *(uint4*)(base + 256 + cg * 16) = make_uint4(lo[0], lo[1], lo[2], lo[3]);
}

// ---------------------------------------------------------------------------
// Kernel 1: hw2 -> fp16 B tiles
// ---------------------------------------------------------------------------
__global__ __launch_bounds__(256) void k_prep_b(const float* __restrict__ hw2) {
    int idx = blockIdx.x * 256 + threadIdx.x;   // 131072
    int n = idx & 127, kc = (idx >> 7) & 15, d = idx >> 11;
    int k0 = kc * 8;
    uint32_t hv[4];
#pragma unroll
    for (int j = 0; j < 4; j++) {
        float v0 = hw2[(k0 + 2 * j) * 8192 + d * 128 + n];
        float v1 = hw2[(k0 + 2 * j + 1) * 8192 + d * 128 + n];
        hv[j] = (uint32_t)__half_as_ushort(__float2half_rn(v0)) |
                ((uint32_t)__half_as_ushort(__float2half_rn(v1)) << 16);
    }
    uint8_t* base = (uint8_t*)g_bbf + d * 34816 + n * 272;
    *(uint4*)(base + k0 * 2) = make_uint4(hv[0], hv[1], hv[2], hv[3]);
}

// ---------------------------------------------------------------------------
// Kernel 2: tail weights -> g_wbf ([k][n] fp16 hi/lo, pitch 528)
// ---------------------------------------------------------------------------
__global__ __launch_bounds__(256) void k_prep_w(
    const float* __restrict__ vw1, const float* __restrict__ vw2,
    const float* __restrict__ aw1, const float* __restrict__ aw2) {
    int idx = blockIdx.x * 256 + threadIdx.x;  // 10240
    int t = idx >> 11;                         // 0..4
    int rem = idx & 2047;
    int k = rem >> 4, c = rem & 15;
    const float* W = (t == 0) ? vw1 : (t == 1) ? vw2 : (t == 2) ? aw1
                     : (t == 3) ? (aw1 + 16384) : aw2;
    uint32_t hi[4], lo[4];
#pragma unroll
    for (int j = 0; j < 4; j++) {
        float2 v = *(const float2*)(W + k * 128 + c * 8 + 2 * j);
        pack_hl2(v.x, v.y, hi[j], lo[j]);
    }
    uint8_t* base = (uint8_t*)g_wbf + t * 67584 + k * 528;
    *(uint4*)(base + c * 16) = make_uint4(hi[0], hi[1], hi[2], hi[3]);
    *(uint4*)(base + 256 + c * 16) = make_uint4(lo[0], lo[1], lo[2], lo[3]);
}

// ---------------------------------------------------------------------------
// Kernel 3: HMMA hypernet. 256 CTAs x 256 thr (2 CTAs/SM).
// CTA = (64-row block rb of 128) x (d-half dh of 2). 8 warps = 2m x 4n.
// smem: sA 33792 | SX 8448 | bias 1024 | B dbl 2x34816 = 112896
// ---------------------------------------------------------------------------
#define SA_OFF    0
#define SX_OFF    33792
#define SBIAS_OFF 42240
#define SB_OFF    43264
#define SB_TILE   34816
#define HSMEM     112896

__global__ __launch_bounds__(256, 2) void k_hyper_mma(const float* __restrict__ hb2) {
    extern __shared__ __align__(128) uint8_t smem[];
    const uint32_t sbase = smem_u32(smem);
    int tid = threadIdx.x, wid = tid >> 5, lane = tid & 31;
    int rb = blockIdx.x >> 1, dh = blockIdx.x & 1;   // rb 0..127 (64-row blocks)
    int n0 = rb * 64, d0 = dh * 32;
    int wm = wid & 1, wn = wid >> 1;                 // 2m x 4n warp grid

    {
        // A tile: 64 consecutive rows within the 128-row image
        const uint4* asrc = &g_abf[(rb >> 1) * 4224 + (rb & 1) * 2112];
        for (int j = tid; j < 2112; j += 256) cp16(sbase + SA_OFF + j * 16, asrc + j);
        const uint4* bsrc = &g_bbf[d0 * 2176];
        for (int j = tid; j < 2176; j += 256) cp16(sbase + SB_OFF + j * 16, bsrc + j);
        if (tid < 32) cp16(sbase + SBIAS_OFF + tid * 16, (const uint4*)(hb2 + d0 * 128) + tid);
        CP_COMMIT();
    }
    float* SX = (float*)(smem + SX_OFF);
    for (int i = tid; i < 64 * 32; i += 256) {
        int r = i >> 5, d = i & 31;
        SX[r * 33 + d] = g_x[(n0 + r) * 64 + d0 + d];
    }

    const int a_r = (lane & 15);
    const int a_kadd = (lane >> 4) * 8;
    const int bm = lane >> 3;
    const int b_n = ((bm >> 1) << 3) + (lane & 7);
    const int b_kadd = (bm & 1) * 8;
    const int r_q = lane >> 2;
    const int c_q = (lane & 3) * 2;

    float emb[2][4][4];
#pragma unroll
    for (int mt = 0; mt < 2; mt++)
#pragma unroll
        for (int t = 0; t < 4; t++)
#pragma unroll
            for (int c = 0; c < 4; c++) emb[mt][t][c] = 0.f;

    for (int i = 0; i < 32; i++) {
        int b = i & 1;
        if (i < 31) {
            const uint4* src = &g_bbf[(d0 + i + 1) * 2176];
            uint32_t dst = sbase + SB_OFF + (1 - b) * SB_TILE;
            for (int j = tid; j < 2176; j += 256) cp16(dst + j * 16, src + j);
            if (tid < 32)
                cp16(sbase + SBIAS_OFF + (1 - b) * 512 + tid * 16,
                     (const uint4*)(hb2 + (d0 + i + 1) * 128) + tid);
            CP_COMMIT();
            CP_WAIT(1);
        } else {
            CP_WAIT(0);
        }
        __syncthreads();

        const uint32_t Ab = sbase + SA_OFF;
        const uint32_t Bb = sbase + SB_OFF + b * SB_TILE;
        float S[2][4][4];
#pragma unroll
        for (int mt = 0; mt < 2; mt++)
#pragma unroll
            for (int t = 0; t < 4; t++)
#pragma unroll
                for (int c = 0; c < 4; c++) S[mt][t][c] = 0.f;

#pragma unroll
        for (int ks = 0; ks < 8; ks++) {
            uint32_t ah[2][4], al[2][4], bh[2][4];
            int ka = ks * 16 + a_kadd;
#pragma unroll
            for (int mt = 0; mt < 2; mt++) {
                int ar = wm * 32 + mt * 16 + a_r;
                ldsm_x4(ah[mt], Ab + ar * 528 + ka * 2);
                ldsm_x4(al[mt], Ab + ar * 528 + 256 + ka * 2);
            }
            int kb = ks * 16 + b_kadd;
#pragma unroll
            for (int nt = 0; nt < 2; nt++) {
                int nr = wn * 32 + nt * 16 + b_n;
                ldsm_x4(bh[nt], Bb + nr * 272 + kb * 2);
            }
#pragma unroll
            for (int mt = 0; mt < 2; mt++)
#pragma unroll
                for (int nt = 0; nt < 2; nt++) {
                    mma16816h(S[mt][nt * 2], ah[mt], bh[nt][0], bh[nt][1]);
                    mma16816h(S[mt][nt * 2], al[mt], bh[nt][0], bh[nt][1]);
                    mma16816h(S[mt][nt * 2 + 1], ah[mt], bh[nt][2], bh[nt][3]);
                    mma16816h(S[mt][nt * 2 + 1], al[mt], bh[nt][2], bh[nt][3]);
                }
        }
        const float* bias = (const float*)(smem + SBIAS_OFF) + b * 128;
#pragma unroll
        for (int mt = 0; mt < 2; mt++) {
            int rbase = wm * 32 + mt * 16 + r_q;
            float xlo = SX[rbase * 33 + i];
            float xhi = SX[(rbase + 8) * 33 + i];
#pragma unroll
            for (int t = 0; t < 4; t++) {
                int col = wn * 32 + t * 8 + c_q;
                float2 bv = *(const float2*)&bias[col];
                float* e = emb[mt][t];
                e[0] += xlo * fmaxf(S[mt][t][0] + bv.x, 0.f);
                e[1] += xlo * fmaxf(S[mt][t][1] + bv.y, 0.f);
                e[2] += xhi * fmaxf(S[mt][t][2] + bv.x, 0.f);
                e[3] += xhi * fmaxf(S[mt][t][3] + bv.y, 0.f);
            }
        }
        __syncthreads();
    }

    float* dst = g_embp + dh * (NTOT * HID) + n0 * 128;
#pragma unroll
    for (int mt = 0; mt < 2; mt++) {
        int row = wm * 32 + mt * 16 + r_q;
#pragma unroll
        for (int t = 0; t < 4; t++) {
            int col = wn * 32 + t * 8 + c_q;
            *(float2*)&dst[row * 128 + col] = make_float2(emb[mt][t][0], emb[mt][t][1]);
            *(float2*)&dst[(row + 8) * 128 + col] = make_float2(emb[mt][t][2], emb[mt][t][3]);
        }
    }
}

// ---------------------------------------------------------------------------
// Kernel 4: combine partials (tanh) -> fp16 hi/lo emb tiles + mean tiles.
// ---------------------------------------------------------------------------
__global__ __launch_bounds__(256) void k_combine_mean() {
    __shared__ float2 red[4][64];
    int b = blockIdx.x, tid = threadIdx.x;
    int c2 = tid & 63, rg = tid >> 6;
    uint8_t* ebase = (uint8_t*)g_ebf + (b >> 3) * 67584 + ((b & 7) * 16) * 528;
    float2 sum = make_float2(0.f, 0.f);
#pragma unroll
    for (int r = 0; r < 4; r++) {
        int row = rg * 4 + r;
        int n = b * 16 + row;
        float2 p0 = *(const float2*)&g_embp[n * 128 + 2 * c2];
        float2 p1 = *(const float2*)&g_embp[NTOT * HID + n * 128 + 2 * c2];
        float v0 = tanhf(p0.x + p1.x), v1 = tanhf(p0.y + p1.y);
        sum.x += v0;
        sum.y += v1;
        uint32_t hi, lo;
        pack_hl2(v0, v1, hi, lo);
        *(uint32_t*)(ebase + row * 528 + c2 * 4) = hi;
        *(uint32_t*)(ebase + row * 528 + 256 + c2 * 4) = lo;
    }
    red[rg][c2] = sum;
    __syncthreads();
    if (rg == 0) {
        float2 m;
        m.x = (red[0][c2].x + red[1][c2].x + red[2][c2].x + red[3][c2].x) * (1.f / 16.f);
        m.y = (red[0][c2].y + red[1][c2].y + red[2][c2].y + red[3][c2].y) * (1.f / 16.f);
        uint32_t hi, lo;
        pack_hl2(m.x, m.y, hi, lo);
        uint8_t* mbase = (uint8_t*)g_mbf + (b >> 7) * 67584 + (b & 127) * 528;
        *(uint32_t*)(mbase + c2 * 4) = hi;
        *(uint32_t*)(mbase + 256 + c2 * 4) = lo;
    }
}

// ---------------------------------------------------------------------------
// Kernel 5: pipelined HMMA tail (unchanged from R9).
// ---------------------------------------------------------------------------
#define TA_OFF  0
#define TW0_OFF 67584
#define TW1_OFF 135168
#define TB_OFF  202752
#define T3_OFF  203776
#define TSMEM   204288

__device__ __forceinline__ void t_layer(uint32_t sbase, uint32_t Wb, int wm, int wn, int lane,
                                        float S[2][4][4]) {
    const int a_r = lane & 15, a_kadd = (lane >> 4) * 8;
    const int b_krow = lane & 15, b_nadd = (lane >> 4) * 8;
    const uint32_t Ab = sbase + TA_OFF;
#pragma unroll
    for (int ks = 0; ks < 8; ks++) {
        uint32_t ah[2][4], al[2][4], wh[2][4], wl[2][4];
        int ka = ks * 16 + a_kadd;
#pragma unroll
        for (int mt = 0; mt < 2; mt++) {
            int ar = wm * 32 + mt * 16 + a_r;
            ldsm_x4(ah[mt], Ab + ar * 528 + ka * 2);
            ldsm_x4(al[mt], Ab + ar * 528 + 256 + ka * 2);
        }
#pragma unroll
        for (int nt = 0; nt < 2; nt++) {
            uint32_t base = Wb + (ks * 16 + b_krow) * 528 + (wn * 32 + nt * 16 + b_nadd) * 2;
            ldsm_x4_t(wh[nt], base);
            ldsm_x4_t(wl[nt], base + 256);
        }
#pragma unroll
        for (int mt = 0; mt < 2; mt++)
#pragma unroll
            for (int nt = 0; nt < 2; nt++) {
                mma16816h(S[mt][nt * 2], ah[mt], wh[nt][0], wh[nt][1]);
                mma16816h(S[mt][nt * 2], al[mt], wh[nt][0], wh[nt][1]);
                mma16816h(S[mt][nt * 2], ah[mt], wl[nt][0], wl[nt][1]);
                mma16816h(S[mt][nt * 2 + 1], ah[mt], wh[nt][2], wh[nt][3]);
                mma16816h(S[mt][nt * 2 + 1], al[mt], wh[nt][2], wh[nt][3]);
                mma16816h(S[mt][nt * 2 + 1], ah[mt], wl[nt][2], wl[nt][3]);
            }
    }
}
__device__ __forceinline__ void t_act_to_sA(uint8_t* smem, const float* bias,
                                            int wm, int wn, int lane, float S[2][4][4]) {
    int r_q = lane >> 2, c_q = (lane & 3) * 2;
#pragma unroll
    for (int mt = 0; mt < 2; mt++) {
        int row = wm * 32 + mt * 16 + r_q;
#pragma unroll
        for (int t = 0; t < 4; t++) {
            int col = wn * 32 + t * 8 + c_q;
            float2 bv = *(const float2*)&bias[col];
            uint32_t hi, lo;
            pack_hl2(fmaxf(S[mt][t][0] + bv.x, 0.f), fmaxf(S[mt][t][1] + bv.y, 0.f), hi, lo);
            *(uint32_t*)(smem + TA_OFF + row * 528 + col * 2) = hi;
            *(uint32_t*)(smem + TA_OFF + row * 528 + 256 + col * 2) = lo;
            pack_hl2(fmaxf(S[mt][t][2] + bv.x, 0.f), fmaxf(S[mt][t][3] + bv.y, 0.f), hi, lo);
            *(uint32_t*)(smem + TA_OFF + (row + 8) * 528 + col * 2) = hi;
            *(uint32_t*)(smem + TA_OFF + (row + 8) * 528 + 256 + col * 2) = lo;
        }
    }
}

__global__ __launch_bounds__(512, 1) void k_tail_mma(
    const float* __restrict__ vb1, const float* __restrict__ vb2,
    const float* __restrict__ ab1, const float* __restrict__ ab2,
    const float* __restrict__ aw3, const float* __restrict__ ab3) {
    extern __shared__ __align__(128) uint8_t smem[];
    const uint32_t sbase = smem_u32(smem);
    int tid = threadIdx.x, wid = tid >> 5, lane = tid & 31;
    int wm = wid & 3, wn = wid >> 2;
    int r_q = lane >> 2, c_q = (lane & 3) * 2;
    float* b0 = (float*)(smem + TB_OFF);
    float* b1 = b0 + 128;

    float S[2][4][4];
#define ZERO_S() { _Pragma("unroll") for (int mt = 0; mt < 2; mt++) \
    _Pragma("unroll") for (int t = 0; t < 4; t++) \
    _Pragma("unroll") for (int c = 0; c < 4; c++) S[mt][t][c] = 0.f; }

    if (blockIdx.x < 64) {
        int n0 = blockIdx.x * 128;
        for (int j = tid; j < 4224; j += 512) cp16(sbase + TA_OFF + j * 16, &g_ebf[blockIdx.x * 4224 + j]);
        for (int j = tid; j < 4224; j += 512) cp16(sbase + TW0_OFF + j * 16, &g_wbf[0 * 4224 + j]);
        CP_COMMIT();
        for (int j = tid; j < 4224; j += 512) cp16(sbase + TW1_OFF + j * 16, &g_wbf[1 * 4224 + j]);
        CP_COMMIT();
        if (tid < 128) b0[tid] = vb1[tid];
        else if (tid < 256) b1[tid - 128] = vb2[tid - 128];
        CP_WAIT(1);
        __syncthreads();
        ZERO_S();
        t_layer(sbase, sbase + TW0_OFF, wm, wn, lane, S);
        __syncthreads();
        t_act_to_sA(smem, b0, wm, wn, lane, S);
        CP_WAIT(0);
        __syncthreads();
        ZERO_S();
        t_layer(sbase, sbase + TW1_OFF, wm, wn, lane, S);
#pragma unroll
        for (int mt = 0; mt < 2; mt++) {
            int row = wm * 32 + mt * 16 + r_q;
#pragma unroll
            for (int t = 0; t < 4; t++) {
                int col = wn * 32 + t * 8 + c_q;
                float2 bv = *(const float2*)&b1[col];
                *(float2*)&g_vals[(n0 + row) * 128 + col] =
                    make_float2(fmaxf(S[mt][t][0] + bv.x, 0.f), fmaxf(S[mt][t][1] + bv.y, 0.f));
                *(float2*)&g_vals[(n0 + row + 8) * 128 + col] =
                    make_float2(fmaxf(S[mt][t][2] + bv.x, 0.f), fmaxf(S[mt][t][3] + bv.y, 0.f));
            }
        }
    } else {
        int cb = blockIdx.x - 64;
        int n0 = cb * 128;
        for (int j = tid; j < 4224; j += 512) cp16(sbase + TA_OFF + j * 16, &g_ebf[cb * 4224 + j]);
        for (int j = tid; j < 4224; j += 512) cp16(sbase + TW0_OFF + j * 16, &g_wbf[2 * 4224 + j]);
        CP_COMMIT();
        for (int j = tid; j < 4224; j += 512) cp16(sbase + TW1_OFF + j * 16, &g_wbf[3 * 4224 + j]);
        CP_COMMIT();
        if (tid < 128) b0[tid] = ab1[tid];
        else if (tid < 256) b1[tid - 128] = ab2[tid - 128];
        else if (tid < 384) ((float*)(smem + T3_OFF))[tid - 256] = aw3[tid - 256];
        CP_WAIT(1);
        __syncthreads();
        ZERO_S();
        t_layer(sbase, sbase + TW0_OFF, wm, wn, lane, S);  // layer1a
        __syncthreads();
        for (int j = tid; j < 4224; j += 512) cp16(sbase + TA_OFF + j * 16, &g_mbf[(cb & 3) * 4224 + j]);
        CP_COMMIT();
        for (int j = tid; j < 4224; j += 512) cp16(sbase + TW0_OFF + j * 16, &g_wbf[4 * 4224 + j]);
        CP_COMMIT();
        CP_WAIT(1);
        __syncthreads();
        t_layer(sbase, sbase + TW1_OFF, wm, wn, lane, S);  // layer1b
        __syncthreads();
        t_act_to_sA(smem, b0, wm, wn, lane, S);
        CP_WAIT(0);
        __syncthreads();
        ZERO_S();
        t_layer(sbase, sbase + TW0_OFF, wm, wn, lane, S);  // layer2
        __syncthreads();
        t_act_to_sA(smem, b1, wm, wn, lane, S);
        __syncthreads();
        const float* sw3 = (const float*)(smem + T3_OFF);
        int row = tid >> 2, l4 = tid & 3;
        float s = 0.f;
#pragma unroll
        for (int j = 0; j < 32; j++) {
            int k = l4 * 32 + j;
            float hi = __half2float(*(const __half*)(smem + TA_OFF + row * 528 + k * 2));
            float lo = __half2float(*(const __half*)(smem + TA_OFF + row * 528 + 256 + k * 2));
            s += (hi + lo) * sw3[k];
        }
        s += __shfl_xor_sync(0xffffffffu, s, 1);
        s += __shfl_xor_sync(0xffffffffu, s, 2);
        if (l4 == 0) g_sc[n0 + row] = s + ab3[0];
    }
}

// ---------------------------------------------------------------------------
// Kernel 6: softmax over 16 + weighted sum -> out[512,128]
// ---------------------------------------------------------------------------
__global__ void k_final(float* __restrict__ out) {
    __shared__ float sc[NADV];
    int b = blockIdx.x, tid = threadIdx.x;
    if (tid < NADV) sc[tid] = g_sc[b * NADV + tid];
    __syncthreads();
    float m = sc[0];
#pragma unroll
    for (int a = 1; a < NADV; a++) m = fmaxf(m, sc[a]);
    float den = 0.f, o = 0.f;
#pragma unroll
    for (int a = 0; a < NADV; a++) {
        float e = expf(sc[a] - m);
        den += e;
        o += e * g_vals[(b * NADV + a) * HID + tid];
    }
    out[b * HID + tid] = o / den;
}

// ---------------------------------------------------------------------------
extern "C" void kernel_launch(void* const* d_in, const int* in_sizes, int n_in,
                              void* d_out, int out_size) {
    const float* obs = (const float*)d_in[0];
    const float* lat = (const float*)d_in[1];
    const float* hw1 = (const float*)d_in[2];
    const float* hb1 = (const float*)d_in[3];
    const float* hw2 = (const float*)d_in[4];
    const float* hb2 = (const float*)d_in[5];
    const float* vw1 = (const float*)d_in[6];
    const float* vb1 = (const float*)d_in[7];
    const float* vw2 = (const float*)d_in[8];
    const float* vb2 = (const float*)d_in[9];
    const float* aw1 = (const float*)d_in[10];
    const float* ab1 = (const float*)d_in[11];
    const float* aw2 = (const float*)d_in[12];
    const float* ab2 = (const float*)d_in[13];
    const float* aw3 = (const float*)d_in[14];
    const float* ab3 = (const float*)d_in[15];
    float* out = (float*)d_out;

    static int attr_set = 0;
    if (!attr_set) {
        cudaFuncSetAttribute(k_hyper_mma, cudaFuncAttributeMaxDynamicSharedMemorySize, HSMEM);
        cudaFuncSetAttribute(k_tail_mma, cudaFuncAttributeMaxDynamicSharedMemorySize, TSMEM);
        attr_set = 1;
    }

    k_h1<<<NTOT / 16, 256>>>(obs, lat, hw1, hb1);                      // 0
    k_prep_b<<<512, 256>>>(hw2);                                       // 1
    k_prep_w<<<40, 256>>>(vw1, vw2, aw1, aw2);                         // 2
    k_hyper_mma<<<256, 256, HSMEM>>>(hb2);                             // 3 (ncu slot)
    k_combine_mean<<<BATCH, 256>>>();                                  // 4
    k_tail_mma<<<128, 512, TSMEM>>>(vb1, vb2, ab1, ab2, aw3, ab3);     // 5
    k_final<<<BATCH, HID>>>(out);                                      // 6
}

// round 11
// speedup vs baseline: 8.7746x; 1.3104x over previous
#include <cuda_runtime.h>
#include <cuda_fp16.h>
#include <math.h>
#include <stdint.h>

// Problem constants
#define NTOT 8192   // B * A
#define BATCH 512
#define NADV 16
#define DIN 64      // DS + DO
#define HID 128

// Scratch
__device__ float g_x[NTOT * DIN];
__device__ float g_embp[2 * NTOT * HID];   // partial einsum sums (pre-tanh)
__device__ float g_vals[NTOT * HID];
__device__ float g_sc[NTOT];
// Hyper A tiles: fp16 hi only, pitch 272B; 128-row tile = 34816B = 2176 uint4
__device__ uint4 g_abf[64 * 2176];
// Tail tiles: fp16 hi/lo, pitch 528B; 128-row tile = 67584B = 4224 uint4
__device__ uint4 g_ebf[64 * 4224];   // emb tiles (tail A)
__device__ uint4 g_mbf[4 * 4224];    // mean tiles
__device__ uint4 g_wbf[5 * 4224];    // tail weights: vw1,vw2,aw1a,aw1b,aw2 ([k][n])
// Hyper B tiles: fp16 hi only, pitch 272B; tile = 34816B = 2176 uint4
__device__ uint4 g_bbf[64 * 2176];

// ---------------------------------------------------------------------------
// helpers
// ---------------------------------------------------------------------------
__device__ __forceinline__ uint32_t smem_u32(const void* p) {
    uint32_t a;
    asm("{ .reg .u64 t; cvta.to.shared.u64 t, %1; cvt.u32.u64 %0, t; }" : "=r"(a) : "l"(p));
    return a;
}
__device__ __forceinline__ void f2hl16(float v, uint16_t& h, uint16_t& l) {
    __half hh = __float2half_rn(v);
    float r = v - __half2float(hh);
    __half hl = __float2half_rn(r);
    h = __half_as_ushort(hh);
    l = __half_as_ushort(hl);
}
__device__ __forceinline__ void pack_hl2(float v0, float v1, uint32_t& hi, uint32_t& lo) {
    uint16_t h0, l0, h1, l1;
    f2hl16(v0, h0, l0);
    f2hl16(v1, h1, l1);
    hi = (uint32_t)h0 | ((uint32_t)h1 << 16);
    lo = (uint32_t)l0 | ((uint32_t)l1 << 16);
}
__device__ __forceinline__ uint32_t pack_h2(float v0, float v1) {
    return (uint32_t)__half_as_ushort(__float2half_rn(v0)) |
           ((uint32_t)__half_as_ushort(__float2half_rn(v1)) << 16);
}
__device__ __forceinline__ void ldsm_x4(uint32_t* r, uint32_t addr) {
    asm volatile("ldmatrix.sync.aligned.m8n8.x4.shared.b16 {%0,%1,%2,%3}, [%4];"
                 : "=r"(r[0]), "=r"(r[1]), "=r"(r[2]), "=r"(r[3]) : "r"(addr));
}
__device__ __forceinline__ void ldsm_x4_t(uint32_t* r, uint32_t addr) {
    asm volatile("ldmatrix.sync.aligned.m8n8.x4.trans.shared.b16 {%0,%1,%2,%3}, [%4];"
                 : "=r"(r[0]), "=r"(r[1]), "=r"(r[2]), "=r"(r[3]) : "r"(addr));
}
__device__ __forceinline__ void mma16816h(float* d, const uint32_t* a, uint32_t b0, uint32_t b1) {
    asm volatile(
        "mma.sync.aligned.m16n8k16.row.col.f32.f16.f16.f32 "
        "{%0,%1,%2,%3}, {%4,%5,%6,%7}, {%8,%9}, {%0,%1,%2,%3};"
        : "+f"(d[0]), "+f"(d[1]), "+f"(d[2]), "+f"(d[3])
        : "r"(a[0]), "r"(a[1]), "r"(a[2]), "r"(a[3]), "r"(b0), "r"(b1));
}
__device__ __forceinline__ void cp16(uint32_t dst, const void* src) {
    asm volatile("cp.async.cg.shared.global [%0], [%1], 16;" :: "r"(dst), "l"(src) : "memory");
}
#define CP_COMMIT() asm volatile("cp.async.commit_group;" ::: "memory")
#define CP_WAIT(N)  asm volatile("cp.async.wait_group %0;" :: "n"(N) : "memory")

// ---------------------------------------------------------------------------
// Kernel 0: build h1 -> fp16 (hi-only) A tiles + g_x
// ---------------------------------------------------------------------------
__global__ __launch_bounds__(256) void k_h1(
    const float* __restrict__ obs, const float* __restrict__ lat,
    const float* __restrict__ hw1, const float* __restrict__ hb1) {
    __shared__ __align__(16) float sw[DIN][HID];
    __shared__ float sb[HID];
    __shared__ float sx[16][DIN];
    int tid = threadIdx.x;
    int n0 = blockIdx.x * 16;

    for (int i = tid; i < DIN * HID; i += 256) ((float*)sw)[i] = hw1[i];
    if (tid < HID) sb[tid] = hb1[tid];
    for (int i = tid; i < 16 * DIN; i += 256) {
        int r = i >> 6, d = i & 63;
        int n = n0 + r;
        float v = (d < 32) ? obs[(n & 511) * 32 + d] : lat[n * 32 + (d - 32)];
        sx[r][d] = v;
        g_x[n * DIN + d] = v;
    }
    __syncthreads();

    int r = tid >> 4, cg = tid & 15;
    float acc[8];
#pragma unroll
    for (int c = 0; c < 8; c++) acc[c] = 0.f;
#pragma unroll 8
    for (int d = 0; d < DIN; d++) {
        float a = sx[r][d];
        float4 w0 = *(const float4*)&sw[d][cg * 8];
        float4 w1 = *(const float4*)&sw[d][cg * 8 + 4];
        acc[0] += a * w0.x; acc[1] += a * w0.y;
        acc[2] += a * w0.z; acc[3] += a * w0.w;
        acc[4] += a * w1.x; acc[5] += a * w1.y;
        acc[6] += a * w1.z; acc[7] += a * w1.w;
    }
    int n = n0 + r;
    uint32_t hv[4];
#pragma unroll
    for (int j = 0; j < 4; j++)
        hv[j] = pack_h2(fmaxf(acc[2 * j] + sb[cg * 8 + 2 * j], 0.f),
                        fmaxf(acc[2 * j + 1] + sb[cg * 8 + 2 * j + 1], 0.f));
    uint8_t* base = (uint8_t*)g_abf + (n >> 7) * 34816 + (n & 127) * 272;
    *(uint4*)(base + cg * 16) = make_uint4(hv[0], hv[1], hv[2], hv[3]);
}

// ---------------------------------------------------------------------------
// Kernel 1: hw2 -> fp16 B tiles
// ---------------------------------------------------------------------------
__global__ __launch_bounds__(256) void k_prep_b(const float* __restrict__ hw2) {
    int idx = blockIdx.x * 256 + threadIdx.x;   // 131072
    int n = idx & 127, kc = (idx >> 7) & 15, d = idx >> 11;
    int k0 = kc * 8;
    uint32_t hv[4];
#pragma unroll
    for (int j = 0; j < 4; j++) {
        float v0 = hw2[(k0 + 2 * j) * 8192 + d * 128 + n];
        float v1 = hw2[(k0 + 2 * j + 1) * 8192 + d * 128 + n];
        hv[j] = pack_h2(v0, v1);
    }
    uint8_t* base = (uint8_t*)g_bbf + d * 34816 + n * 272;
    *(uint4*)(base + k0 * 2) = make_uint4(hv[0], hv[1], hv[2], hv[3]);
}

// ---------------------------------------------------------------------------
// Kernel 2: tail weights -> g_wbf ([k][n] fp16 hi/lo, pitch 528)
// ---------------------------------------------------------------------------
__global__ __launch_bounds__(256) void k_prep_w(
    const float* __restrict__ vw1, const float* __restrict__ vw2,
    const float* __restrict__ aw1, const float* __restrict__ aw2) {
    int idx = blockIdx.x * 256 + threadIdx.x;  // 10240
    int t = idx >> 11;                         // 0..4
    int rem = idx & 2047;
    int k = rem >> 4, c = rem & 15;
    const float* W = (t == 0) ? vw1 : (t == 1) ? vw2 : (t == 2) ? aw1
                     : (t == 3) ? (aw1 + 16384) : aw2;
    uint32_t hi[4], lo[4];
#pragma unroll
    for (int j = 0; j < 4; j++) {
        float2 v = *(const float2*)(W + k * 128 + c * 8 + 2 * j);
        pack_hl2(v.x, v.y, hi[j], lo[j]);
    }
    uint8_t* base = (uint8_t*)g_wbf + t * 67584 + k * 528;
    *(uint4*)(base + c * 16) = make_uint4(hi[0], hi[1], hi[2], hi[3]);
    *(uint4*)(base + 256 + c * 16) = make_uint4(lo[0], lo[1], lo[2], lo[3]);
}

// ---------------------------------------------------------------------------
// Kernel 3: HMMA hypernet, SINGLE-PASS fp16 (A_hi x B_hi).
// 256 CTAs x 256 thr (2 CTAs/SM). CTA = 64-row block x d-half. 8 warps 2m x 4n.
// smem: sA 17408 | SX 8448 | bias 1024 | B dbl 2x34816 = 96512
// ---------------------------------------------------------------------------
#define SA_OFF    0
#define SX_OFF    17408
#define SBIAS_OFF 25856
#define SB_OFF    26880
#define SB_TILE   34816
#define HSMEM     96512

__global__ __launch_bounds__(256, 2) void k_hyper_mma(const float* __restrict__ hb2) {
    extern __shared__ __align__(128) uint8_t smem[];
    const uint32_t sbase = smem_u32(smem);
    int tid = threadIdx.x, wid = tid >> 5, lane = tid & 31;
    int rb = blockIdx.x >> 1, dh = blockIdx.x & 1;   // rb 0..127 (64-row blocks)
    int n0 = rb * 64, d0 = dh * 32;
    int wm = wid & 1, wn = wid >> 1;                 // 2m x 4n warp grid

    {
        // A tile: 64 rows, hi-only (1088 uint4)
        const uint4* asrc = &g_abf[(rb >> 1) * 2176 + (rb & 1) * 1088];
        for (int j = tid; j < 1088; j += 256) cp16(sbase + SA_OFF + j * 16, asrc + j);
        const uint4* bsrc = &g_bbf[d0 * 2176];
        for (int j = tid; j < 2176; j += 256) cp16(sbase + SB_OFF + j * 16, bsrc + j);
        if (tid < 32) cp16(sbase + SBIAS_OFF + tid * 16, (const uint4*)(hb2 + d0 * 128) + tid);
        CP_COMMIT();
    }
    float* SX = (float*)(smem + SX_OFF);
    for (int i = tid; i < 64 * 32; i += 256) {
        int r = i >> 5, d = i & 31;
        SX[r * 33 + d] = g_x[(n0 + r) * 64 + d0 + d];
    }

    const int a_r = (lane & 15);
    const int a_kadd = (lane >> 4) * 8;
    const int bm = lane >> 3;
    const int b_n = ((bm >> 1) << 3) + (lane & 7);
    const int b_kadd = (bm & 1) * 8;
    const int r_q = lane >> 2;
    const int c_q = (lane & 3) * 2;

    float emb[2][4][4];
#pragma unroll
    for (int mt = 0; mt < 2; mt++)
#pragma unroll
        for (int t = 0; t < 4; t++)
#pragma unroll
            for (int c = 0; c < 4; c++) emb[mt][t][c] = 0.f;

    for (int i = 0; i < 32; i++) {
        int b = i & 1;
        if (i < 31) {
            const uint4* src = &g_bbf[(d0 + i + 1) * 2176];
            uint32_t dst = sbase + SB_OFF + (1 - b) * SB_TILE;
            for (int j = tid; j < 2176; j += 256) cp16(dst + j * 16, src + j);
            if (tid < 32)
                cp16(sbase + SBIAS_OFF + (1 - b) * 512 + tid * 16,
                     (const uint4*)(hb2 + (d0 + i + 1) * 128) + tid);
            CP_COMMIT();
            CP_WAIT(1);
        } else {
            CP_WAIT(0);
        }
        __syncthreads();

        const uint32_t Ab = sbase + SA_OFF;
        const uint32_t Bb = sbase + SB_OFF + b * SB_TILE;
        float S[2][4][4];
#pragma unroll
        for (int mt = 0; mt < 2; mt++)
#pragma unroll
            for (int t = 0; t < 4; t++)
#pragma unroll
                for (int c = 0; c < 4; c++) S[mt][t][c] = 0.f;

#pragma unroll
        for (int ks = 0; ks < 8; ks++) {
            uint32_t ah[2][4], bh[2][4];
            int ka = ks * 16 + a_kadd;
#pragma unroll
            for (int mt = 0; mt < 2; mt++) {
                int ar = wm * 32 + mt * 16 + a_r;
                ldsm_x4(ah[mt], Ab + ar * 272 + ka * 2);
            }
            int kb = ks * 16 + b_kadd;
#pragma unroll
            for (int nt = 0; nt < 2; nt++) {
                int nr = wn * 32 + nt * 16 + b_n;
                ldsm_x4(bh[nt], Bb + nr * 272 + kb * 2);
            }
#pragma unroll
            for (int mt = 0; mt < 2; mt++)
#pragma unroll
                for (int nt = 0; nt < 2; nt++) {
                    mma16816h(S[mt][nt * 2], ah[mt], bh[nt][0], bh[nt][1]);
                    mma16816h(S[mt][nt * 2 + 1], ah[mt], bh[nt][2], bh[nt][3]);
                }
        }
        const float* bias = (const float*)(smem + SBIAS_OFF) + b * 128;
#pragma unroll
        for (int mt = 0; mt < 2; mt++) {
            int rbase = wm * 32 + mt * 16 + r_q;
            float xlo = SX[rbase * 33 + i];
            float xhi = SX[(rbase + 8) * 33 + i];
#pragma unroll
            for (int t = 0; t < 4; t++) {
                int col = wn * 32 + t * 8 + c_q;
                float2 bv = *(const float2*)&bias[col];
                float* e = emb[mt][t];
                e[0] += xlo * fmaxf(S[mt][t][0] + bv.x, 0.f);
                e[1] += xlo * fmaxf(S[mt][t][1] + bv.y, 0.f);
                e[2] += xhi * fmaxf(S[mt][t][2] + bv.x, 0.f);
                e[3] += xhi * fmaxf(S[mt][t][3] + bv.y, 0.f);
            }
        }
        __syncthreads();
    }

    float* dst = g_embp + dh * (NTOT * HID) + n0 * 128;
#pragma unroll
    for (int mt = 0; mt < 2; mt++) {
        int row = wm * 32 + mt * 16 + r_q;
#pragma unroll
        for (int t = 0; t < 4; t++) {
            int col = wn * 32 + t * 8 + c_q;
            *(float2*)&dst[row * 128 + col] = make_float2(emb[mt][t][0], emb[mt][t][1]);
            *(float2*)&dst[(row + 8) * 128 + col] = make_float2(emb[mt][t][2], emb[mt][t][3]);
        }
    }
}

// ---------------------------------------------------------------------------
// Kernel 4: combine partials (tanh) -> fp16 hi/lo emb tiles + mean tiles.
// ---------------------------------------------------------------------------
__global__ __launch_bounds__(256) void k_combine_mean() {
    __shared__ float2 red[4][64];
    int b = blockIdx.x, tid = threadIdx.x;
    int c2 = tid & 63, rg = tid >> 6;
    uint8_t* ebase = (uint8_t*)g_ebf + (b >> 3) * 67584 + ((b & 7) * 16) * 528;
    float2 sum = make_float2(0.f, 0.f);
#pragma unroll
    for (int r = 0; r < 4; r++) {
        int row = rg * 4 + r;
        int n = b * 16 + row;
        float2 p0 = *(const float2*)&g_embp[n * 128 + 2 * c2];
        float2 p1 = *(const float2*)&g_embp[NTOT * HID + n * 128 + 2 * c2];
        float v0 = tanhf(p0.x + p1.x), v1 = tanhf(p0.y + p1.y);
        sum.x += v0;
        sum.y += v1;
        uint32_t hi, lo;
        pack_hl2(v0, v1, hi, lo);
        *(uint32_t*)(ebase + row * 528 + c2 * 4) = hi;
        *(uint32_t*)(ebase + row * 528 + 256 + c2 * 4) = lo;
    }
    red[rg][c2] = sum;
    __syncthreads();
    if (rg == 0) {
        float2 m;
        m.x = (red[0][c2].x + red[1][c2].x + red[2][c2].x + red[3][c2].x) * (1.f / 16.f);
        m.y = (red[0][c2].y + red[1][c2].y + red[2][c2].y + red[3][c2].y) * (1.f / 16.f);
        uint32_t hi, lo;
        pack_hl2(m.x, m.y, hi, lo);
        uint8_t* mbase = (uint8_t*)g_mbf + (b >> 7) * 67584 + (b & 127) * 528;
        *(uint32_t*)(mbase + c2 * 4) = hi;
        *(uint32_t*)(mbase + 256 + c2 * 4) = lo;
    }
}

// ---------------------------------------------------------------------------
// Kernel 5: pipelined HMMA tail (3-pass, unchanged from R10).
// ---------------------------------------------------------------------------
#define TA_OFF  0
#define TW0_OFF 67584
#define TW1_OFF 135168
#define TB_OFF  202752
#define T3_OFF  203776
#define TSMEM   204288

__device__ __forceinline__ void t_layer(uint32_t sbase, uint32_t Wb, int wm, int wn, int lane,
                                        float S[2][4][4]) {
    const int a_r = lane & 15, a_kadd = (lane >> 4) * 8;
    const int b_krow = lane & 15, b_nadd = (lane >> 4) * 8;
    const uint32_t Ab = sbase + TA_OFF;
#pragma unroll
    for (int ks = 0; ks < 8; ks++) {
        uint32_t ah[2][4], al[2][4], wh[2][4], wl[2][4];
        int ka = ks * 16 + a_kadd;
#pragma unroll
        for (int mt = 0; mt < 2; mt++) {
            int ar = wm * 32 + mt * 16 + a_r;
            ldsm_x4(ah[mt], Ab + ar * 528 + ka * 2);
            ldsm_x4(al[mt], Ab + ar * 528 + 256 + ka * 2);
        }
#pragma unroll
        for (int nt = 0; nt < 2; nt++) {
            uint32_t base = Wb + (ks * 16 + b_krow) * 528 + (wn * 32 + nt * 16 + b_nadd) * 2;
            ldsm_x4_t(wh[nt], base);
            ldsm_x4_t(wl[nt], base + 256);
        }
#pragma unroll
        for (int mt = 0; mt < 2; mt++)
#pragma unroll
            for (int nt = 0; nt < 2; nt++) {
                mma16816h(S[mt][nt * 2], ah[mt], wh[nt][0], wh[nt][1]);
                mma16816h(S[mt][nt * 2], al[mt], wh[nt][0], wh[nt][1]);
                mma16816h(S[mt][nt * 2], ah[mt], wl[nt][0], wl[nt][1]);
                mma16816h(S[mt][nt * 2 + 1], ah[mt], wh[nt][2], wh[nt][3]);
                mma16816h(S[mt][nt * 2 + 1], al[mt], wh[nt][2], wh[nt][3]);
                mma16816h(S[mt][nt * 2 + 1], ah[mt], wl[nt][2], wl[nt][3]);
            }
    }
}
__device__ __forceinline__ void t_act_to_sA(uint8_t* smem, const float* bias,
                                            int wm, int wn, int lane, float S[2][4][4]) {
    int r_q = lane >> 2, c_q = (lane & 3) * 2;
#pragma unroll
    for (int mt = 0; mt < 2; mt++) {
        int row = wm * 32 + mt * 16 + r_q;
#pragma unroll
        for (int t = 0; t < 4; t++) {
            int col = wn * 32 + t * 8 + c_q;
            float2 bv = *(const float2*)&bias[col];
            uint32_t hi, lo;
            pack_hl2(fmaxf(S[mt][t][0] + bv.x, 0.f), fmaxf(S[mt][t][1] + bv.y, 0.f), hi, lo);
            *(uint32_t*)(smem + TA_OFF + row * 528 + col * 2) = hi;
            *(uint32_t*)(smem + TA_OFF + row * 528 + 256 + col * 2) = lo;
            pack_hl2(fmaxf(S[mt][t][2] + bv.x, 0.f), fmaxf(S[mt][t][3] + bv.y, 0.f), hi, lo);
            *(uint32_t*)(smem + TA_OFF + (row + 8) * 528 + col * 2) = hi;
            *(uint32_t*)(smem + TA_OFF + (row + 8) * 528 + 256 + col * 2) = lo;
        }
    }
}

__global__ __launch_bounds__(512, 1) void k_tail_mma(
    const float* __restrict__ vb1, const float* __restrict__ vb2,
    const float* __restrict__ ab1, const float* __restrict__ ab2,
    const float* __restrict__ aw3, const float* __restrict__ ab3) {
    extern __shared__ __align__(128) uint8_t smem[];
    const uint32_t sbase = smem_u32(smem);
    int tid = threadIdx.x, wid = tid >> 5, lane = tid & 31;
    int wm = wid & 3, wn = wid >> 2;
    int r_q = lane >> 2, c_q = (lane & 3) * 2;
    float* b0 = (float*)(smem + TB_OFF);
    float* b1 = b0 + 128;

    float S[2][4][4];
#define ZERO_S() { _Pragma("unroll") for (int mt = 0; mt < 2; mt++) \
    _Pragma("unroll") for (int t = 0; t < 4; t++) \
    _Pragma("unroll") for (int c = 0; c < 4; c++) S[mt][t][c] = 0.f; }

    if (blockIdx.x < 64) {
        int n0 = blockIdx.x * 128;
        for (int j = tid; j < 4224; j += 512) cp16(sbase + TA_OFF + j * 16, &g_ebf[blockIdx.x * 4224 + j]);
        for (int j = tid; j < 4224; j += 512) cp16(sbase + TW0_OFF + j * 16, &g_wbf[0 * 4224 + j]);
        CP_COMMIT();
        for (int j = tid; j < 4224; j += 512) cp16(sbase + TW1_OFF + j * 16, &g_wbf[1 * 4224 + j]);
        CP_COMMIT();
        if (tid < 128) b0[tid] = vb1[tid];
        else if (tid < 256) b1[tid - 128] = vb2[tid - 128];
        CP_WAIT(1);
        __syncthreads();
        ZERO_S();
        t_layer(sbase, sbase + TW0_OFF, wm, wn, lane, S);
        __syncthreads();
        t_act_to_sA(smem, b0, wm, wn, lane, S);
        CP_WAIT(0);
        __syncthreads();
        ZERO_S();
        t_layer(sbase, sbase + TW1_OFF, wm, wn, lane, S);
#pragma unroll
        for (int mt = 0; mt < 2; mt++) {
            int row = wm * 32 + mt * 16 + r_q;
#pragma unroll
            for (int t = 0; t < 4; t++) {
                int col = wn * 32 + t * 8 + c_q;
                float2 bv = *(const float2*)&b1[col];
                *(float2*)&g_vals[(n0 + row) * 128 + col] =
                    make_float2(fmaxf(S[mt][t][0] + bv.x, 0.f), fmaxf(S[mt][t][1] + bv.y, 0.f));
                *(float2*)&g_vals[(n0 + row + 8) * 128 + col] =
                    make_float2(fmaxf(S[mt][t][2] + bv.x, 0.f), fmaxf(S[mt][t][3] + bv.y, 0.f));
            }
        }
    } else {
        int cb = blockIdx.x - 64;
        int n0 = cb * 128;
        for (int j = tid; j < 4224; j += 512) cp16(sbase + TA_OFF + j * 16, &g_ebf[cb * 4224 + j]);
        for (int j = tid; j < 4224; j += 512) cp16(sbase + TW0_OFF + j * 16, &g_wbf[2 * 4224 + j]);
        CP_COMMIT();
        for (int j = tid; j < 4224; j += 512) cp16(sbase + TW1_OFF + j * 16, &g_wbf[3 * 4224 + j]);
        CP_COMMIT();
        if (tid < 128) b0[tid] = ab1[tid];
        else if (tid < 256) b1[tid - 128] = ab2[tid - 128];
        else if (tid < 384) ((float*)(smem + T3_OFF))[tid - 256] = aw3[tid - 256];
        CP_WAIT(1);
        __syncthreads();
        ZERO_S();
        t_layer(sbase, sbase + TW0_OFF, wm, wn, lane, S);  // layer1a
        __syncthreads();
        for (int j = tid; j < 4224; j += 512) cp16(sbase + TA_OFF + j * 16, &g_mbf[(cb & 3) * 4224 + j]);
        CP_COMMIT();
        for (int j = tid; j < 4224; j += 512) cp16(sbase + TW0_OFF + j * 16, &g_wbf[4 * 4224 + j]);
        CP_COMMIT();
        CP_WAIT(1);
        __syncthreads();
        t_layer(sbase, sbase + TW1_OFF, wm, wn, lane, S);  // layer1b
        __syncthreads();
        t_act_to_sA(smem, b0, wm, wn, lane, S);
        CP_WAIT(0);
        __syncthreads();
        ZERO_S();
        t_layer(sbase, sbase + TW0_OFF, wm, wn, lane, S);  // layer2
        __syncthreads();
        t_act_to_sA(smem, b1, wm, wn, lane, S);
        __syncthreads();
        const float* sw3 = (const float*)(smem + T3_OFF);
        int row = tid >> 2, l4 = tid & 3;
        float s = 0.f;
#pragma unroll
        for (int j = 0; j < 32; j++) {
            int k = l4 * 32 + j;
            float hi = __half2float(*(const __half*)(smem + TA_OFF + row * 528 + k * 2));
            float lo = __half2float(*(const __half*)(smem + TA_OFF + row * 528 + 256 + k * 2));
            s += (hi + lo) * sw3[k];
        }
        s += __shfl_xor_sync(0xffffffffu, s, 1);
        s += __shfl_xor_sync(0xffffffffu, s, 2);
        if (l4 == 0) g_sc[n0 + row] = s + ab3[0];
    }
}

// ---------------------------------------------------------------------------
// Kernel 6: softmax over 16 + weighted sum -> out[512,128]
// ---------------------------------------------------------------------------
__global__ void k_final(float* __restrict__ out) {
    __shared__ float sc[NADV];
    int b = blockIdx.x, tid = threadIdx.x;
    if (tid < NADV) sc[tid] = g_sc[b * NADV + tid];
    __syncthreads();
    float m = sc[0];
#pragma unroll
    for (int a = 1; a < NADV; a++) m = fmaxf(m, sc[a]);
    float den = 0.f, o = 0.f;
#pragma unroll
    for (int a = 0; a < NADV; a++) {
        float e = expf(sc[a] - m);
        den += e;
        o += e * g_vals[(b * NADV + a) * HID + tid];
    }
    out[b * HID + tid] = o / den;
}

// ---------------------------------------------------------------------------
extern "C" void kernel_launch(void* const* d_in, const int* in_sizes, int n_in,
                              void* d_out, int out_size) {
    const float* obs = (const float*)d_in[0];
    const float* lat = (const float*)d_in[1];
    const float* hw1 = (const float*)d_in[2];
    const float* hb1 = (const float*)d_in[3];
    const float* hw2 = (const float*)d_in[4];
    const float* hb2 = (const float*)d_in[5];
    const float* vw1 = (const float*)d_in[6];
    const float* vb1 = (const float*)d_in[7];
    const float* vw2 = (const float*)d_in[8];
    const float* vb2 = (const float*)d_in[9];
    const float* aw1 = (const float*)d_in[10];
    const float* ab1 = (const float*)d_in[11];
    const float* aw2 = (const float*)d_in[12];
    const float* ab2 = (const float*)d_in[13];
    const float* aw3 = (const float*)d_in[14];
    const float* ab3 = (const float*)d_in[15];
    float* out = (float*)d_out;

    static int attr_set = 0;
    if (!attr_set) {
        cudaFuncSetAttribute(k_hyper_mma, cudaFuncAttributeMaxDynamicSharedMemorySize, HSMEM);
        cudaFuncSetAttribute(k_tail_mma, cudaFuncAttributeMaxDynamicSharedMemorySize, TSMEM);
        attr_set = 1;
    }

    k_h1<<<NTOT / 16, 256>>>(obs, lat, hw1, hb1);                      // 0
    k_prep_b<<<512, 256>>>(hw2);                                       // 1
    k_prep_w<<<40, 256>>>(vw1, vw2, aw1, aw2);                         // 2
    k_hyper_mma<<<256, 256, HSMEM>>>(hb2);                             // 3 (ncu slot)
    k_combine_mean<<<BATCH, 256>>>();                                  // 4
    k_tail_mma<<<128, 512, TSMEM>>>(vb1, vb2, ab1, ab2, aw3, ab3);     // 5
    k_final<<<BATCH, HID>>>(out);                                      // 6
}